// round 12
// baseline (speedup 1.0000x reference)
#include <cuda_runtime.h>
#include <cuda_fp16.h>
#include <cstdint>

#define BDIM 1024
#define NH 16
#define HD 64
#define BB 2
#define SEQ 2048
#define MTOT (BB*SEQ)
#define QK_SCALE 0.1803368801111204f   // 0.125 * log2(e)

// scratch (device globals — allocation-guard safe). Referenced ONLY from
// device code (host-passing gives host shadow addrs — the R4/R5 bug).
__device__ __half g_Q [(long)BB*NH*SEQ*HD];     // Q pre-scaled by QK_SCALE
__device__ __half g_K [(long)BB*NH*SEQ*HD];
__device__ __half g_Vt[(long)BB*NH*HD*SEQ];     // V transposed: [b,h,d,n]
__device__ __half g_O [(long)MTOT*BDIM];        // attention out, head-concat
__device__ __half g_Xh[(long)MTOT*BDIM];
__device__ __half g_Wh[(long)3*BDIM*BDIM];
__device__ __half g_PWh[(long)BDIM*BDIM];

// ---------------------------------------------------------------------------
// helpers
// ---------------------------------------------------------------------------
__device__ __forceinline__ float ex2f(float x) {
    float y;
    asm("ex2.approx.ftz.f32 %0, %1;" : "=f"(y) : "f"(x));
    return y;
}
__device__ __forceinline__ uint32_t smem_u32(const void* p) {
    uint32_t a;
    asm("{ .reg .u64 t; cvta.to.shared.u64 t, %1; cvt.u32.u64 %0, t; }" : "=r"(a) : "l"(p));
    return a;
}
__device__ __forceinline__ void cp16(uint32_t dst, const void* src) {
    asm volatile("cp.async.cg.shared.global [%0], [%1], 16;" :: "r"(dst), "l"(src) : "memory");
}
__device__ __forceinline__ uint32_t packh2(float lo, float hi) {
    __half2 h = __floats2half2_rn(lo, hi);
    return *(uint32_t*)&h;
}
__device__ __forceinline__ void ldsm4(uint32_t* r, uint32_t addr) {
    asm volatile("ldmatrix.sync.aligned.m8n8.x4.shared.b16 {%0,%1,%2,%3}, [%4];"
                 : "=r"(r[0]), "=r"(r[1]), "=r"(r[2]), "=r"(r[3]) : "r"(addr));
}
// mma.sync m16n8k16 f16 -> f32
__device__ __forceinline__ void mma_f16(float c[4],
                                        uint32_t a0, uint32_t a1, uint32_t a2, uint32_t a3,
                                        uint32_t b0, uint32_t b1) {
    asm volatile(
        "mma.sync.aligned.m16n8k16.row.col.f32.f16.f16.f32 "
        "{%0,%1,%2,%3}, {%4,%5,%6,%7}, {%8,%9}, {%0,%1,%2,%3};"
        : "+f"(c[0]), "+f"(c[1]), "+f"(c[2]), "+f"(c[3])
        : "r"(a0), "r"(a1), "r"(a2), "r"(a3), "r"(b0), "r"(b1));
}

// ---------------------------------------------------------------------------
// prepass: fp32 -> fp16 copies of x, qkv_w, proj_w
// ---------------------------------------------------------------------------
__global__ void half_prep(const float* __restrict__ x, const float* __restrict__ w,
                          const float* __restrict__ pw)
{
    int y = blockIdx.y;
    const float4* src;
    uint2* dst;
    long n4;
    if (y == 0)      { src = (const float4*)x;  dst = (uint2*)g_Xh;  n4 = (long)MTOT*BDIM/4; }
    else if (y == 1) { src = (const float4*)w;  dst = (uint2*)g_Wh;  n4 = (long)3*BDIM*BDIM/4; }
    else             { src = (const float4*)pw; dst = (uint2*)g_PWh; n4 = (long)BDIM*BDIM/4; }
    long stride = (long)gridDim.x * blockDim.x;
    for (long i = (long)blockIdx.x*blockDim.x + threadIdx.x; i < n4; i += stride) {
        float4 v = src[i];
        uint2 u;
        u.x = packh2(v.x, v.y);
        u.y = packh2(v.z, v.w);
        dst[i] = u;
    }
}

// ---------------------------------------------------------------------------
// FP16 GEMM v2: CTA tile 256x128, warp tile 64x64 (8 warps, 4x2), 1 CTA/SM.
// mma.sync m16n8k16 + ldmatrix + cp.async 3-stage, SW128 smem.
// Fragment replication falls from x3 to x2 -> crossbar traffic/MAC -33%.
//   MODE 0: A=g_Xh, W=g_Wh,  epilogue -> half Q(scaled)/K/[Vt transposed]
//   MODE 1: A=g_O,  W=g_PWh, epilogue -> fp32 row-major C
// ---------------------------------------------------------------------------
#define STG_A 32768              // 256 rows x 128B
#define STG_B 16384              // 128 rows x 128B
#define STG   (STG_A + STG_B)    // 49152
#define NST   3                  // 147456 B

template<int MODE>
__global__ __launch_bounds__(256, 1)
void gemm_h(const float* __restrict__ bias, float* __restrict__ Cout,
            int K, int Nout)
{
    extern __shared__ char smem[];
    uint32_t sbase = smem_u32(smem);
    const __half* Ab = (MODE == 1) ? (const __half*)g_O  : (const __half*)g_Xh;
    const __half* Wb = (MODE == 1) ? (const __half*)g_PWh : (const __half*)g_Wh;

    int tid = threadIdx.x, warp = tid >> 5, lane = tid & 31;
    int g = lane >> 2, t = lane & 3;
    int wm = (warp >> 1) * 64, wn = (warp & 1) * 64;
    int m0 = blockIdx.y * 256, n0 = blockIdx.x * 128;

    // cp.async mapping: 8 A-chunks + 4 B-chunks (16B) per thread per stage
    int aoff[8]; uint32_t adst[8];
    #pragma unroll
    for (int i = 0; i < 8; i++) {
        int cid = i*256 + tid;              // 0..2047
        int row = cid >> 3, ch = cid & 7;   // row 0..255
        adst[i] = (uint32_t)(row*128 + ((ch ^ (row & 7)) << 4));
        aoff[i] = (m0 + row)*K + ch*8;
    }
    int boff[4]; uint32_t bdst[4];
    #pragma unroll
    for (int i = 0; i < 4; i++) {
        int cid = i*256 + tid;              // 0..1023
        int row = cid >> 3, ch = cid & 7;   // row 0..127
        bdst[i] = (uint32_t)(STG_A + row*128 + ((ch ^ (row & 7)) << 4));
        boff[i] = (n0 + row)*K + ch*8;
    }

    // ldmatrix lane addressing
    int lr16 = lane & 15;
    uint32_t hs = (uint32_t)(lane >> 4);
    uint32_t cx = (uint32_t)(lane & 7);
    uint32_t ar128[4], br128[4];
    #pragma unroll
    for (int mt = 0; mt < 4; mt++) ar128[mt] = (uint32_t)(wm + mt*16 + lr16) * 128u;
    #pragma unroll
    for (int p = 0; p < 4; p++)    br128[p] = (uint32_t)(wn + p*16 + lr16) * 128u;

    float acc[4][8][4];
    #pragma unroll
    for (int i = 0; i < 4; i++)
        #pragma unroll
        for (int j = 0; j < 8; j++)
            #pragma unroll
            for (int c = 0; c < 4; c++) acc[i][j][c] = 0.f;

    int niter = K >> 6;

    #pragma unroll
    for (int s = 0; s < 2; s++) {
        uint32_t db = sbase + s*STG;
        #pragma unroll
        for (int i = 0; i < 8; i++) cp16(db + adst[i], Ab + aoff[i] + s*64);
        #pragma unroll
        for (int i = 0; i < 4; i++) cp16(db + bdst[i], Wb + boff[i] + s*64);
        asm volatile("cp.async.commit_group;" ::: "memory");
    }

    for (int it = 0; it < niter; ++it) {
        asm volatile("cp.async.wait_group 1;" ::: "memory");
        __syncthreads();

        int nx = it + 2;
        if (nx < niter) {
            uint32_t db = sbase + (nx % NST)*STG;
            int koff = nx * 64;
            #pragma unroll
            for (int i = 0; i < 8; i++) cp16(db + adst[i], Ab + aoff[i] + koff);
            #pragma unroll
            for (int i = 0; i < 4; i++) cp16(db + bdst[i], Wb + boff[i] + koff);
        }
        asm volatile("cp.async.commit_group;" ::: "memory");

        uint32_t sA = sbase + (it % NST)*STG;
        uint32_t sB = sA + STG_A;

        #pragma unroll
        for (int kk = 0; kk < 4; kk++) {
            uint32_t sw = ((2u*kk + hs) ^ cx) << 4;
            uint32_t af[4][4], bf[4][4];
            #pragma unroll
            for (int mt = 0; mt < 4; mt++) ldsm4(af[mt], sA + ar128[mt] + sw);
            #pragma unroll
            for (int p = 0; p < 4; p++)    ldsm4(bf[p], sB + br128[p] + sw);
            #pragma unroll
            for (int mt = 0; mt < 4; mt++) {
                #pragma unroll
                for (int p = 0; p < 4; p++) {
                    mma_f16(acc[mt][2*p],   af[mt][0], af[mt][1], af[mt][2], af[mt][3],
                            bf[p][0], bf[p][2]);
                    mma_f16(acc[mt][2*p+1], af[mt][0], af[mt][1], af[mt][2], af[mt][3],
                            bf[p][1], bf[p][3]);
                }
            }
        }
    }

    // epilogue
    #pragma unroll
    for (int mt = 0; mt < 4; mt++) {
        int rowA = m0 + wm + mt*16 + g;
        int rowB = rowA + 8;
        #pragma unroll
        for (int nt = 0; nt < 8; nt++) {
            int col = n0 + wn + nt*8 + 2*t;
            float b0v = bias[col], b1v = bias[col+1];
            float2 va = make_float2(acc[mt][nt][0] + b0v, acc[mt][nt][1] + b1v);
            float2 vb = make_float2(acc[mt][nt][2] + b0v, acc[mt][nt][3] + b1v);
            if (MODE == 0) {
                int which = col >> 10;
                int c = col & (BDIM - 1);
                int hh = c >> 6, d = c & 63;
                int bA = rowA >> 11, nA = rowA & (SEQ - 1);
                int bR = rowB >> 11, nR = rowB & (SEQ - 1);
                if (which == 0) {
                    va.x *= QK_SCALE; va.y *= QK_SCALE;
                    vb.x *= QK_SCALE; vb.y *= QK_SCALE;
                    *(uint32_t*)(g_Q + ((((long)bA*NH + hh)*SEQ) + nA)*HD + d) = packh2(va.x, va.y);
                    *(uint32_t*)(g_Q + ((((long)bR*NH + hh)*SEQ) + nR)*HD + d) = packh2(vb.x, vb.y);
                } else if (which == 1) {
                    *(uint32_t*)(g_K + ((((long)bA*NH + hh)*SEQ) + nA)*HD + d) = packh2(va.x, va.y);
                    *(uint32_t*)(g_K + ((((long)bR*NH + hh)*SEQ) + nR)*HD + d) = packh2(vb.x, vb.y);
                } else {                 // V transposed: [b,h,d,n]
                    __half* vt = g_Vt;
                    long baseA = (((long)bA*NH + hh)*HD);
                    long baseB = (((long)bR*NH + hh)*HD);
                    vt[(baseA + d  )*SEQ + nA] = __float2half_rn(va.x);
                    vt[(baseA + d+1)*SEQ + nA] = __float2half_rn(va.y);
                    vt[(baseB + d  )*SEQ + nR] = __float2half_rn(vb.x);
                    vt[(baseB + d+1)*SEQ + nR] = __float2half_rn(vb.y);
                }
            } else {
                *(float2*)(Cout + (long)rowA * Nout + col) = va;
                *(float2*)(Cout + (long)rowB * Nout + col) = vb;
            }
        }
    }
}

// ---------------------------------------------------------------------------
// FP16 flash attention — R9 configuration verbatim (proven best):
// 8 warps x 32 q-rows (256 q-rows/CTA), 64-key tiles, SW128 K/Vt smem,
// ldmatrix frags, cp.async 3-stage. S C-frag == PV A-frag identity.
// ---------------------------------------------------------------------------
#define KBY 8192                     // 64 rows x 128B
#define ABUF (2*KBY)
#define ANST 3                       // 48 KB

__global__ __launch_bounds__(256, 1)
void attn_h()
{
    extern __shared__ __align__(16) char dsm[];

    int tid  = threadIdx.x;
    int lane = tid & 31, warp = tid >> 5;      // warp 0..7
    int g = lane >> 2, t = lane & 3;
    int b = blockIdx.z, h = blockIdx.y;
    const __half* Qb  = g_Q  + ((long)(b*NH + h)) * SEQ * HD;
    const __half* Kb  = g_K  + ((long)(b*NH + h)) * SEQ * HD;
    const __half* Vtb = g_Vt + ((long)(b*NH + h)) * HD * SEQ;

    int qn = blockIdx.x * 256 + warp * 32;

    uint32_t sb = smem_u32(dsm);
    uint32_t kdo[2];
    const __half* ksrc[2];
    const __half* vsrc[2];
    #pragma unroll
    for (int i = 0; i < 2; i++) {
        int cid = i*256 + tid;
        int row = cid >> 3, ch = cid & 7;          // row 0..63
        kdo[i] = (uint32_t)(row*128 + ((ch ^ (row & 7)) << 4));
        ksrc[i] = Kb  + (long)row*HD  + ch*8;      // +64*HD per tile
        vsrc[i] = Vtb + (long)row*SEQ + ch*8;      // +64 per tile
    }

    int lr16 = lane & 15;
    uint32_t hs = (uint32_t)(lane >> 4);
    uint32_t cx = (uint32_t)(lane & 7);
    uint32_t r128[4];
    #pragma unroll
    for (int p = 0; p < 4; p++) r128[p] = (uint32_t)(p*16 + lr16) * 128u;

    uint32_t qf[4][2][4];
    #pragma unroll
    for (int mt = 0; mt < 2; mt++) {
        const uint32_t* q0 = (const uint32_t*)(Qb + (long)(qn + mt*16 + g) * HD);
        const uint32_t* q1 = (const uint32_t*)(Qb + (long)(qn + mt*16 + g + 8) * HD);
        #pragma unroll
        for (int kk = 0; kk < 4; kk++) {
            qf[kk][mt][0] = q0[kk*8 + t];
            qf[kk][mt][1] = q1[kk*8 + t];
            qf[kk][mt][2] = q0[kk*8 + t + 4];
            qf[kk][mt][3] = q1[kk*8 + t + 4];
        }
    }

    float oacc[2][8][4];
    #pragma unroll
    for (int mt = 0; mt < 2; mt++)
        #pragma unroll
        for (int i = 0; i < 8; i++)
            #pragma unroll
            for (int j = 0; j < 4; j++) oacc[mt][i][j] = 0.f;
    float mA[2] = {-1e30f, -1e30f}, mB[2] = {-1e30f, -1e30f};
    float lA[2] = {0.f, 0.f},       lB[2] = {0.f, 0.f};

    #pragma unroll
    for (int s = 0; s < 2; s++) {
        uint32_t so = (uint32_t)s * ABUF;
        #pragma unroll
        for (int i = 0; i < 2; i++) {
            cp16(sb + so + kdo[i],       ksrc[i] + (long)s*64*HD);
            cp16(sb + so + KBY + kdo[i], vsrc[i] + s*64);
        }
        asm volatile("cp.async.commit_group;" ::: "memory");
    }

    const int NT = SEQ/64;
    for (int kt = 0; kt < NT; ++kt) {
        asm volatile("cp.async.wait_group 1;" ::: "memory");
        __syncthreads();

        if (kt + 2 < NT) {
            uint32_t so = (uint32_t)((kt+2) % ANST) * ABUF;
            #pragma unroll
            for (int i = 0; i < 2; i++) {
                cp16(sb + so + kdo[i],       ksrc[i] + (long)(kt+2)*64*HD);
                cp16(sb + so + KBY + kdo[i], vsrc[i] + (kt+2)*64);
            }
        }
        asm volatile("cp.async.commit_group;" ::: "memory");

        uint32_t sK = sb + (kt % ANST)*ABUF;
        uint32_t sV = sK + KBY;

        // S = Q @ K^T (log2 units)
        float sc[2][8][4];
        #pragma unroll
        for (int mt = 0; mt < 2; mt++)
            #pragma unroll
            for (int i = 0; i < 8; i++)
                #pragma unroll
                for (int j = 0; j < 4; j++) sc[mt][i][j] = 0.f;
        #pragma unroll
        for (int kk = 0; kk < 4; kk++) {
            uint32_t sw = ((2u*kk + hs) ^ cx) << 4;
            uint32_t kb[4][4];
            #pragma unroll
            for (int p = 0; p < 4; p++) ldsm4(kb[p], sK + r128[p] + sw);
            #pragma unroll
            for (int p = 0; p < 4; p++) {
                #pragma unroll
                for (int mt = 0; mt < 2; mt++) {
                    mma_f16(sc[mt][2*p],   qf[kk][mt][0], qf[kk][mt][1], qf[kk][mt][2], qf[kk][mt][3],
                            kb[p][0], kb[p][2]);
                    mma_f16(sc[mt][2*p+1], qf[kk][mt][0], qf[kk][mt][1], qf[kk][mt][2], qf[kk][mt][3],
                            kb[p][1], kb[p][3]);
                }
            }
        }

        // online softmax per m-tile
        #pragma unroll
        for (int mt = 0; mt < 2; mt++) {
            float mlA = -1e30f, mlB = -1e30f;
            #pragma unroll
            for (int nt = 0; nt < 8; nt++) {
                mlA = fmaxf(mlA, fmaxf(sc[mt][nt][0], sc[mt][nt][1]));
                mlB = fmaxf(mlB, fmaxf(sc[mt][nt][2], sc[mt][nt][3]));
            }
            mlA = fmaxf(mlA, __shfl_xor_sync(0xffffffffu, mlA, 1));
            mlA = fmaxf(mlA, __shfl_xor_sync(0xffffffffu, mlA, 2));
            mlB = fmaxf(mlB, __shfl_xor_sync(0xffffffffu, mlB, 1));
            mlB = fmaxf(mlB, __shfl_xor_sync(0xffffffffu, mlB, 2));
            float mnA = fmaxf(mA[mt], mlA), mnB = fmaxf(mB[mt], mlB);
            float cA = ex2f(mA[mt] - mnA), cB = ex2f(mB[mt] - mnB);
            lA[mt] *= cA; lB[mt] *= cB;
            #pragma unroll
            for (int nt = 0; nt < 8; nt++) {
                oacc[mt][nt][0] *= cA; oacc[mt][nt][1] *= cA;
                oacc[mt][nt][2] *= cB; oacc[mt][nt][3] *= cB;
            }
            #pragma unroll
            for (int nt = 0; nt < 8; nt++) {
                float p0 = ex2f(sc[mt][nt][0] - mnA);
                float p1 = ex2f(sc[mt][nt][1] - mnA);
                float p2 = ex2f(sc[mt][nt][2] - mnB);
                float p3 = ex2f(sc[mt][nt][3] - mnB);
                lA[mt] += p0 + p1; lB[mt] += p2 + p3;
                sc[mt][nt][0] = p0; sc[mt][nt][1] = p1;
                sc[mt][nt][2] = p2; sc[mt][nt][3] = p3;
            }
            mA[mt] = mnA; mB[mt] = mnB;
        }

        // O += P @ V : S C-frag IS the PV A-frag; V frags via ldmatrix
        #pragma unroll
        for (int kk = 0; kk < 4; kk++) {
            uint32_t sw = ((2u*kk + hs) ^ cx) << 4;
            uint32_t Af[2][4];
            #pragma unroll
            for (int mt = 0; mt < 2; mt++) {
                Af[mt][0] = packh2(sc[mt][2*kk][0],   sc[mt][2*kk][1]);
                Af[mt][1] = packh2(sc[mt][2*kk][2],   sc[mt][2*kk][3]);
                Af[mt][2] = packh2(sc[mt][2*kk+1][0], sc[mt][2*kk+1][1]);
                Af[mt][3] = packh2(sc[mt][2*kk+1][2], sc[mt][2*kk+1][3]);
            }
            uint32_t vb[4][4];
            #pragma unroll
            for (int p = 0; p < 4; p++) ldsm4(vb[p], sV + r128[p] + sw);
            #pragma unroll
            for (int p = 0; p < 4; p++) {
                #pragma unroll
                for (int mt = 0; mt < 2; mt++) {
                    mma_f16(oacc[mt][2*p],   Af[mt][0], Af[mt][1], Af[mt][2], Af[mt][3],
                            vb[p][0], vb[p][2]);
                    mma_f16(oacc[mt][2*p+1], Af[mt][0], Af[mt][1], Af[mt][2], Af[mt][3],
                            vb[p][1], vb[p][3]);
                }
            }
        }
    }

    // finalize
    #pragma unroll
    for (int mt = 0; mt < 2; mt++) {
        float la = lA[mt], lb = lB[mt];
        la += __shfl_xor_sync(0xffffffffu, la, 1);
        la += __shfl_xor_sync(0xffffffffu, la, 2);
        lb += __shfl_xor_sync(0xffffffffu, lb, 1);
        lb += __shfl_xor_sync(0xffffffffu, lb, 2);
        float iA = 1.f / la, iB = 1.f / lb;

        __half* OA = g_O + ((long)(b*SEQ) + qn + mt*16 + g) * BDIM + h*HD;
        __half* OB = OA + 8*BDIM;
        #pragma unroll
        for (int nt = 0; nt < 8; nt++) {
            int c = nt*8 + 2*t;
            *(uint32_t*)(OA + c) = packh2(oacc[mt][nt][0]*iA, oacc[mt][nt][1]*iA);
            *(uint32_t*)(OB + c) = packh2(oacc[mt][nt][2]*iB, oacc[mt][nt][3]*iB);
        }
    }
}

// ---------------------------------------------------------------------------
extern "C" void kernel_launch(void* const* d_in, const int* in_sizes, int n_in,
                              void* d_out, int out_size)
{
    const float* x      = (const float*)d_in[0];
    const float* qkv_w  = (const float*)d_in[1];
    const float* qkv_b  = (const float*)d_in[2];
    const float* proj_w = (const float*)d_in[3];
    const float* proj_b = (const float*)d_in[4];
    float* out = (float*)d_out;

    int shmem  = NST * STG;      // 147456
    int ashmem = ANST * ABUF;    // 49152
    cudaFuncSetAttribute(gemm_h<0>, cudaFuncAttributeMaxDynamicSharedMemorySize, shmem);
    cudaFuncSetAttribute(gemm_h<1>, cudaFuncAttributeMaxDynamicSharedMemorySize, shmem);
    cudaFuncSetAttribute(attn_h, cudaFuncAttributeMaxDynamicSharedMemorySize, ashmem);

    half_prep<<<dim3(1024, 3), 256>>>(x, qkv_w, proj_w);

    dim3 g_qkv(3*BDIM/128, MTOT/256);   // (24, 16)
    gemm_h<0><<<g_qkv, 256, shmem>>>(qkv_b, nullptr, BDIM, 3*BDIM);

    dim3 g_attn(SEQ/256, NH, BB);       // (8, 16, 2)
    attn_h<<<g_attn, 256, ashmem>>>();

    dim3 g_proj(BDIM/128, MTOT/256);    // (8, 16)
    gemm_h<1><<<g_proj, 256, shmem>>>(proj_b, out, BDIM, BDIM);
}

// round 13
// speedup vs baseline: 1.0009x; 1.0009x over previous
#include <cuda_runtime.h>
#include <cuda_fp16.h>
#include <cstdint>

#define BDIM 1024
#define NH 16
#define HD 64
#define BB 2
#define SEQ 2048
#define MTOT (BB*SEQ)
#define QK_SCALE 0.1803368801111204f   // 0.125 * log2(e)

// scratch (device globals — allocation-guard safe). Referenced ONLY from
// device code (host-passing gives host shadow addrs — the R4/R5 bug).
__device__ __half g_Q [(long)BB*NH*SEQ*HD];     // Q pre-scaled by QK_SCALE
__device__ __half g_K [(long)BB*NH*SEQ*HD];
__device__ __half g_Vt[(long)BB*NH*HD*SEQ];     // V transposed: [b,h,d,n]
__device__ __half g_O [(long)MTOT*BDIM];        // attention out, head-concat
__device__ __half g_Xh[(long)MTOT*BDIM];
__device__ __half g_Wh[(long)3*BDIM*BDIM];
__device__ __half g_PWh[(long)BDIM*BDIM];

// ---------------------------------------------------------------------------
// helpers
// ---------------------------------------------------------------------------
__device__ __forceinline__ float ex2f(float x) {
    float y;
    asm("ex2.approx.ftz.f32 %0, %1;" : "=f"(y) : "f"(x));
    return y;
}
__device__ __forceinline__ uint32_t smem_u32(const void* p) {
    uint32_t a;
    asm("{ .reg .u64 t; cvta.to.shared.u64 t, %1; cvt.u32.u64 %0, t; }" : "=r"(a) : "l"(p));
    return a;
}
__device__ __forceinline__ void cp16(uint32_t dst, const void* src) {
    asm volatile("cp.async.cg.shared.global [%0], [%1], 16;" :: "r"(dst), "l"(src) : "memory");
}
__device__ __forceinline__ uint32_t packh2(float lo, float hi) {
    __half2 h = __floats2half2_rn(lo, hi);
    return *(uint32_t*)&h;
}
__device__ __forceinline__ void ldsm4(uint32_t* r, uint32_t addr) {
    asm volatile("ldmatrix.sync.aligned.m8n8.x4.shared.b16 {%0,%1,%2,%3}, [%4];"
                 : "=r"(r[0]), "=r"(r[1]), "=r"(r[2]), "=r"(r[3]) : "r"(addr));
}
// mma.sync m16n8k16 f16 -> f32
__device__ __forceinline__ void mma_f16(float c[4],
                                        uint32_t a0, uint32_t a1, uint32_t a2, uint32_t a3,
                                        uint32_t b0, uint32_t b1) {
    asm volatile(
        "mma.sync.aligned.m16n8k16.row.col.f32.f16.f16.f32 "
        "{%0,%1,%2,%3}, {%4,%5,%6,%7}, {%8,%9}, {%0,%1,%2,%3};"
        : "+f"(c[0]), "+f"(c[1]), "+f"(c[2]), "+f"(c[3])
        : "r"(a0), "r"(a1), "r"(a2), "r"(a3), "r"(b0), "r"(b1));
}

// ---------------------------------------------------------------------------
// prepass: fp32 -> fp16 copies of x, qkv_w, proj_w
// ---------------------------------------------------------------------------
__global__ void half_prep(const float* __restrict__ x, const float* __restrict__ w,
                          const float* __restrict__ pw)
{
    int y = blockIdx.y;
    const float4* src;
    uint2* dst;
    long n4;
    if (y == 0)      { src = (const float4*)x;  dst = (uint2*)g_Xh;  n4 = (long)MTOT*BDIM/4; }
    else if (y == 1) { src = (const float4*)w;  dst = (uint2*)g_Wh;  n4 = (long)3*BDIM*BDIM/4; }
    else             { src = (const float4*)pw; dst = (uint2*)g_PWh; n4 = (long)BDIM*BDIM/4; }
    long stride = (long)gridDim.x * blockDim.x;
    for (long i = (long)blockIdx.x*blockDim.x + threadIdx.x; i < n4; i += stride) {
        float4 v = src[i];
        uint2 u;
        u.x = packh2(v.x, v.y);
        u.y = packh2(v.z, v.w);
        dst[i] = u;
    }
}

// ---------------------------------------------------------------------------
// FP16 GEMM v3: CTA tile 256x128, warp tile 64x64 (8 warps, 4x2), 1 CTA/SM,
// mma.sync m16n8k16 + ldmatrix + cp.async 3-stage, SW128 smem, and
// DOUBLE-BUFFERED FRAGMENTS: kk+1's ldsm issues before kk's MMAs so ldsm
// latency hides under tensor work (the R12 profile showed latency-bound).
//   MODE 0: A=g_Xh, W=g_Wh,  epilogue -> half Q(scaled)/K/[Vt transposed]
//   MODE 1: A=g_O,  W=g_PWh, epilogue -> fp32 row-major C
// ---------------------------------------------------------------------------
#define STG_A 32768              // 256 rows x 128B
#define STG_B 16384              // 128 rows x 128B
#define STG   (STG_A + STG_B)    // 49152
#define NST   3                  // 147456 B

template<int MODE>
__global__ __launch_bounds__(256, 1)
void gemm_h(const float* __restrict__ bias, float* __restrict__ Cout,
            int K, int Nout)
{
    extern __shared__ char smem[];
    uint32_t sbase = smem_u32(smem);
    const __half* Ab = (MODE == 1) ? (const __half*)g_O  : (const __half*)g_Xh;
    const __half* Wb = (MODE == 1) ? (const __half*)g_PWh : (const __half*)g_Wh;

    int tid = threadIdx.x, warp = tid >> 5, lane = tid & 31;
    int g = lane >> 2, t = lane & 3;
    int wm = (warp >> 1) * 64, wn = (warp & 1) * 64;
    int m0 = blockIdx.y * 256, n0 = blockIdx.x * 128;

    // cp.async mapping: 8 A-chunks + 4 B-chunks (16B) per thread per stage
    int aoff[8]; uint32_t adst[8];
    #pragma unroll
    for (int i = 0; i < 8; i++) {
        int cid = i*256 + tid;              // 0..2047
        int row = cid >> 3, ch = cid & 7;   // row 0..255
        adst[i] = (uint32_t)(row*128 + ((ch ^ (row & 7)) << 4));
        aoff[i] = (m0 + row)*K + ch*8;
    }
    int boff[4]; uint32_t bdst[4];
    #pragma unroll
    for (int i = 0; i < 4; i++) {
        int cid = i*256 + tid;              // 0..1023
        int row = cid >> 3, ch = cid & 7;   // row 0..127
        bdst[i] = (uint32_t)(STG_A + row*128 + ((ch ^ (row & 7)) << 4));
        boff[i] = (n0 + row)*K + ch*8;
    }

    // ldmatrix lane addressing
    int lr16 = lane & 15;
    uint32_t hs = (uint32_t)(lane >> 4);
    uint32_t cx = (uint32_t)(lane & 7);
    uint32_t ar128[4], br128[4];
    #pragma unroll
    for (int mt = 0; mt < 4; mt++) ar128[mt] = (uint32_t)(wm + mt*16 + lr16) * 128u;
    #pragma unroll
    for (int p = 0; p < 4; p++)    br128[p] = (uint32_t)(wn + p*16 + lr16) * 128u;

    float acc[4][8][4];
    #pragma unroll
    for (int i = 0; i < 4; i++)
        #pragma unroll
        for (int j = 0; j < 8; j++)
            #pragma unroll
            for (int c = 0; c < 4; c++) acc[i][j][c] = 0.f;

    int niter = K >> 6;

    #pragma unroll
    for (int s = 0; s < 2; s++) {
        uint32_t db = sbase + s*STG;
        #pragma unroll
        for (int i = 0; i < 8; i++) cp16(db + adst[i], Ab + aoff[i] + s*64);
        #pragma unroll
        for (int i = 0; i < 4; i++) cp16(db + bdst[i], Wb + boff[i] + s*64);
        asm volatile("cp.async.commit_group;" ::: "memory");
    }

    uint32_t af[2][4][4], bf[2][4][4];   // double-buffered fragments

    for (int it = 0; it < niter; ++it) {
        asm volatile("cp.async.wait_group 1;" ::: "memory");
        __syncthreads();

        int nx = it + 2;
        if (nx < niter) {
            uint32_t db = sbase + (nx % NST)*STG;
            int koff = nx * 64;
            #pragma unroll
            for (int i = 0; i < 8; i++) cp16(db + adst[i], Ab + aoff[i] + koff);
            #pragma unroll
            for (int i = 0; i < 4; i++) cp16(db + bdst[i], Wb + boff[i] + koff);
        }
        asm volatile("cp.async.commit_group;" ::: "memory");

        uint32_t sA = sbase + (it % NST)*STG;
        uint32_t sB = sA + STG_A;

        // preload kk=0 fragments
        {
            uint32_t sw = (hs ^ cx) << 4;
            #pragma unroll
            for (int mt = 0; mt < 4; mt++) ldsm4(af[0][mt], sA + ar128[mt] + sw);
            #pragma unroll
            for (int p = 0; p < 4; p++)    ldsm4(bf[0][p], sB + br128[p] + sw);
        }

        #pragma unroll
        for (int kk = 0; kk < 4; kk++) {
            int cur = kk & 1, nxt = cur ^ 1;
            if (kk < 3) {
                uint32_t sw = ((2u*(kk+1) + hs) ^ cx) << 4;
                #pragma unroll
                for (int mt = 0; mt < 4; mt++) ldsm4(af[nxt][mt], sA + ar128[mt] + sw);
                #pragma unroll
                for (int p = 0; p < 4; p++)    ldsm4(bf[nxt][p], sB + br128[p] + sw);
            }
            #pragma unroll
            for (int mt = 0; mt < 4; mt++) {
                #pragma unroll
                for (int p = 0; p < 4; p++) {
                    mma_f16(acc[mt][2*p],   af[cur][mt][0], af[cur][mt][1], af[cur][mt][2], af[cur][mt][3],
                            bf[cur][p][0], bf[cur][p][2]);
                    mma_f16(acc[mt][2*p+1], af[cur][mt][0], af[cur][mt][1], af[cur][mt][2], af[cur][mt][3],
                            bf[cur][p][1], bf[cur][p][3]);
                }
            }
        }
    }

    // epilogue
    #pragma unroll
    for (int mt = 0; mt < 4; mt++) {
        int rowA = m0 + wm + mt*16 + g;
        int rowB = rowA + 8;
        #pragma unroll
        for (int nt = 0; nt < 8; nt++) {
            int col = n0 + wn + nt*8 + 2*t;
            float b0v = bias[col], b1v = bias[col+1];
            float2 va = make_float2(acc[mt][nt][0] + b0v, acc[mt][nt][1] + b1v);
            float2 vb = make_float2(acc[mt][nt][2] + b0v, acc[mt][nt][3] + b1v);
            if (MODE == 0) {
                int which = col >> 10;
                int c = col & (BDIM - 1);
                int hh = c >> 6, d = c & 63;
                int bA = rowA >> 11, nA = rowA & (SEQ - 1);
                int bR = rowB >> 11, nR = rowB & (SEQ - 1);
                if (which == 0) {
                    va.x *= QK_SCALE; va.y *= QK_SCALE;
                    vb.x *= QK_SCALE; vb.y *= QK_SCALE;
                    *(uint32_t*)(g_Q + ((((long)bA*NH + hh)*SEQ) + nA)*HD + d) = packh2(va.x, va.y);
                    *(uint32_t*)(g_Q + ((((long)bR*NH + hh)*SEQ) + nR)*HD + d) = packh2(vb.x, vb.y);
                } else if (which == 1) {
                    *(uint32_t*)(g_K + ((((long)bA*NH + hh)*SEQ) + nA)*HD + d) = packh2(va.x, va.y);
                    *(uint32_t*)(g_K + ((((long)bR*NH + hh)*SEQ) + nR)*HD + d) = packh2(vb.x, vb.y);
                } else {                 // V transposed: [b,h,d,n]
                    __half* vt = g_Vt;
                    long baseA = (((long)bA*NH + hh)*HD);
                    long baseB = (((long)bR*NH + hh)*HD);
                    vt[(baseA + d  )*SEQ + nA] = __float2half_rn(va.x);
                    vt[(baseA + d+1)*SEQ + nA] = __float2half_rn(va.y);
                    vt[(baseB + d  )*SEQ + nR] = __float2half_rn(vb.x);
                    vt[(baseB + d+1)*SEQ + nR] = __float2half_rn(vb.y);
                }
            } else {
                *(float2*)(Cout + (long)rowA * Nout + col) = va;
                *(float2*)(Cout + (long)rowB * Nout + col) = vb;
            }
        }
    }
}

// ---------------------------------------------------------------------------
// FP16 flash attention — R9 configuration verbatim (proven best):
// 8 warps x 32 q-rows (256 q-rows/CTA), 64-key tiles, SW128 K/Vt smem,
// ldmatrix frags, cp.async 3-stage. S C-frag == PV A-frag identity.
// ---------------------------------------------------------------------------
#define KBY 8192                     // 64 rows x 128B
#define ABUF (2*KBY)
#define ANST 3                       // 48 KB

__global__ __launch_bounds__(256, 1)
void attn_h()
{
    extern __shared__ __align__(16) char dsm[];

    int tid  = threadIdx.x;
    int lane = tid & 31, warp = tid >> 5;      // warp 0..7
    int g = lane >> 2, t = lane & 3;
    int b = blockIdx.z, h = blockIdx.y;
    const __half* Qb  = g_Q  + ((long)(b*NH + h)) * SEQ * HD;
    const __half* Kb  = g_K  + ((long)(b*NH + h)) * SEQ * HD;
    const __half* Vtb = g_Vt + ((long)(b*NH + h)) * HD * SEQ;

    int qn = blockIdx.x * 256 + warp * 32;

    uint32_t sb = smem_u32(dsm);
    uint32_t kdo[2];
    const __half* ksrc[2];
    const __half* vsrc[2];
    #pragma unroll
    for (int i = 0; i < 2; i++) {
        int cid = i*256 + tid;
        int row = cid >> 3, ch = cid & 7;          // row 0..63
        kdo[i] = (uint32_t)(row*128 + ((ch ^ (row & 7)) << 4));
        ksrc[i] = Kb  + (long)row*HD  + ch*8;      // +64*HD per tile
        vsrc[i] = Vtb + (long)row*SEQ + ch*8;      // +64 per tile
    }

    int lr16 = lane & 15;
    uint32_t hs = (uint32_t)(lane >> 4);
    uint32_t cx = (uint32_t)(lane & 7);
    uint32_t r128[4];
    #pragma unroll
    for (int p = 0; p < 4; p++) r128[p] = (uint32_t)(p*16 + lr16) * 128u;

    uint32_t qf[4][2][4];
    #pragma unroll
    for (int mt = 0; mt < 2; mt++) {
        const uint32_t* q0 = (const uint32_t*)(Qb + (long)(qn + mt*16 + g) * HD);
        const uint32_t* q1 = (const uint32_t*)(Qb + (long)(qn + mt*16 + g + 8) * HD);
        #pragma unroll
        for (int kk = 0; kk < 4; kk++) {
            qf[kk][mt][0] = q0[kk*8 + t];
            qf[kk][mt][1] = q1[kk*8 + t];
            qf[kk][mt][2] = q0[kk*8 + t + 4];
            qf[kk][mt][3] = q1[kk*8 + t + 4];
        }
    }

    float oacc[2][8][4];
    #pragma unroll
    for (int mt = 0; mt < 2; mt++)
        #pragma unroll
        for (int i = 0; i < 8; i++)
            #pragma unroll
            for (int j = 0; j < 4; j++) oacc[mt][i][j] = 0.f;
    float mA[2] = {-1e30f, -1e30f}, mB[2] = {-1e30f, -1e30f};
    float lA[2] = {0.f, 0.f},       lB[2] = {0.f, 0.f};

    #pragma unroll
    for (int s = 0; s < 2; s++) {
        uint32_t so = (uint32_t)s * ABUF;
        #pragma unroll
        for (int i = 0; i < 2; i++) {
            cp16(sb + so + kdo[i],       ksrc[i] + (long)s*64*HD);
            cp16(sb + so + KBY + kdo[i], vsrc[i] + s*64);
        }
        asm volatile("cp.async.commit_group;" ::: "memory");
    }

    const int NT = SEQ/64;
    for (int kt = 0; kt < NT; ++kt) {
        asm volatile("cp.async.wait_group 1;" ::: "memory");
        __syncthreads();

        if (kt + 2 < NT) {
            uint32_t so = (uint32_t)((kt+2) % ANST) * ABUF;
            #pragma unroll
            for (int i = 0; i < 2; i++) {
                cp16(sb + so + kdo[i],       ksrc[i] + (long)(kt+2)*64*HD);
                cp16(sb + so + KBY + kdo[i], vsrc[i] + (kt+2)*64);
            }
        }
        asm volatile("cp.async.commit_group;" ::: "memory");

        uint32_t sK = sb + (kt % ANST)*ABUF;
        uint32_t sV = sK + KBY;

        // S = Q @ K^T (log2 units)
        float sc[2][8][4];
        #pragma unroll
        for (int mt = 0; mt < 2; mt++)
            #pragma unroll
            for (int i = 0; i < 8; i++)
                #pragma unroll
                for (int j = 0; j < 4; j++) sc[mt][i][j] = 0.f;
        #pragma unroll
        for (int kk = 0; kk < 4; kk++) {
            uint32_t sw = ((2u*kk + hs) ^ cx) << 4;
            uint32_t kb[4][4];
            #pragma unroll
            for (int p = 0; p < 4; p++) ldsm4(kb[p], sK + r128[p] + sw);
            #pragma unroll
            for (int p = 0; p < 4; p++) {
                #pragma unroll
                for (int mt = 0; mt < 2; mt++) {
                    mma_f16(sc[mt][2*p],   qf[kk][mt][0], qf[kk][mt][1], qf[kk][mt][2], qf[kk][mt][3],
                            kb[p][0], kb[p][2]);
                    mma_f16(sc[mt][2*p+1], qf[kk][mt][0], qf[kk][mt][1], qf[kk][mt][2], qf[kk][mt][3],
                            kb[p][1], kb[p][3]);
                }
            }
        }

        // online softmax per m-tile
        #pragma unroll
        for (int mt = 0; mt < 2; mt++) {
            float mlA = -1e30f, mlB = -1e30f;
            #pragma unroll
            for (int nt = 0; nt < 8; nt++) {
                mlA = fmaxf(mlA, fmaxf(sc[mt][nt][0], sc[mt][nt][1]));
                mlB = fmaxf(mlB, fmaxf(sc[mt][nt][2], sc[mt][nt][3]));
            }
            mlA = fmaxf(mlA, __shfl_xor_sync(0xffffffffu, mlA, 1));
            mlA = fmaxf(mlA, __shfl_xor_sync(0xffffffffu, mlA, 2));
            mlB = fmaxf(mlB, __shfl_xor_sync(0xffffffffu, mlB, 1));
            mlB = fmaxf(mlB, __shfl_xor_sync(0xffffffffu, mlB, 2));
            float mnA = fmaxf(mA[mt], mlA), mnB = fmaxf(mB[mt], mlB);
            float cA = ex2f(mA[mt] - mnA), cB = ex2f(mB[mt] - mnB);
            lA[mt] *= cA; lB[mt] *= cB;
            #pragma unroll
            for (int nt = 0; nt < 8; nt++) {
                oacc[mt][nt][0] *= cA; oacc[mt][nt][1] *= cA;
                oacc[mt][nt][2] *= cB; oacc[mt][nt][3] *= cB;
            }
            #pragma unroll
            for (int nt = 0; nt < 8; nt++) {
                float p0 = ex2f(sc[mt][nt][0] - mnA);
                float p1 = ex2f(sc[mt][nt][1] - mnA);
                float p2 = ex2f(sc[mt][nt][2] - mnB);
                float p3 = ex2f(sc[mt][nt][3] - mnB);
                lA[mt] += p0 + p1; lB[mt] += p2 + p3;
                sc[mt][nt][0] = p0; sc[mt][nt][1] = p1;
                sc[mt][nt][2] = p2; sc[mt][nt][3] = p3;
            }
            mA[mt] = mnA; mB[mt] = mnB;
        }

        // O += P @ V : S C-frag IS the PV A-frag; V frags via ldmatrix
        #pragma unroll
        for (int kk = 0; kk < 4; kk++) {
            uint32_t sw = ((2u*kk + hs) ^ cx) << 4;
            uint32_t Af[2][4];
            #pragma unroll
            for (int mt = 0; mt < 2; mt++) {
                Af[mt][0] = packh2(sc[mt][2*kk][0],   sc[mt][2*kk][1]);
                Af[mt][1] = packh2(sc[mt][2*kk][2],   sc[mt][2*kk][3]);
                Af[mt][2] = packh2(sc[mt][2*kk+1][0], sc[mt][2*kk+1][1]);
                Af[mt][3] = packh2(sc[mt][2*kk+1][2], sc[mt][2*kk+1][3]);
            }
            uint32_t vb[4][4];
            #pragma unroll
            for (int p = 0; p < 4; p++) ldsm4(vb[p], sV + r128[p] + sw);
            #pragma unroll
            for (int p = 0; p < 4; p++) {
                #pragma unroll
                for (int mt = 0; mt < 2; mt++) {
                    mma_f16(oacc[mt][2*p],   Af[mt][0], Af[mt][1], Af[mt][2], Af[mt][3],
                            vb[p][0], vb[p][2]);
                    mma_f16(oacc[mt][2*p+1], Af[mt][0], Af[mt][1], Af[mt][2], Af[mt][3],
                            vb[p][1], vb[p][3]);
                }
            }
        }
    }

    // finalize
    #pragma unroll
    for (int mt = 0; mt < 2; mt++) {
        float la = lA[mt], lb = lB[mt];
        la += __shfl_xor_sync(0xffffffffu, la, 1);
        la += __shfl_xor_sync(0xffffffffu, la, 2);
        lb += __shfl_xor_sync(0xffffffffu, lb, 1);
        lb += __shfl_xor_sync(0xffffffffu, lb, 2);
        float iA = 1.f / la, iB = 1.f / lb;

        __half* OA = g_O + ((long)(b*SEQ) + qn + mt*16 + g) * BDIM + h*HD;
        __half* OB = OA + 8*BDIM;
        #pragma unroll
        for (int nt = 0; nt < 8; nt++) {
            int c = nt*8 + 2*t;
            *(uint32_t*)(OA + c) = packh2(oacc[mt][nt][0]*iA, oacc[mt][nt][1]*iA);
            *(uint32_t*)(OB + c) = packh2(oacc[mt][nt][2]*iB, oacc[mt][nt][3]*iB);
        }
    }
}

// ---------------------------------------------------------------------------
extern "C" void kernel_launch(void* const* d_in, const int* in_sizes, int n_in,
                              void* d_out, int out_size)
{
    const float* x      = (const float*)d_in[0];
    const float* qkv_w  = (const float*)d_in[1];
    const float* qkv_b  = (const float*)d_in[2];
    const float* proj_w = (const float*)d_in[3];
    const float* proj_b = (const float*)d_in[4];
    float* out = (float*)d_out;

    int shmem  = NST * STG;      // 147456
    int ashmem = ANST * ABUF;    // 49152
    cudaFuncSetAttribute(gemm_h<0>, cudaFuncAttributeMaxDynamicSharedMemorySize, shmem);
    cudaFuncSetAttribute(gemm_h<1>, cudaFuncAttributeMaxDynamicSharedMemorySize, shmem);
    cudaFuncSetAttribute(attn_h, cudaFuncAttributeMaxDynamicSharedMemorySize, ashmem);

    half_prep<<<dim3(1024, 3), 256>>>(x, qkv_w, proj_w);

    dim3 g_qkv(3*BDIM/128, MTOT/256);   // (24, 16)
    gemm_h<0><<<g_qkv, 256, shmem>>>(qkv_b, nullptr, BDIM, 3*BDIM);

    dim3 g_attn(SEQ/256, NH, BB);       // (8, 16, 2)
    attn_h<<<g_attn, 256, ashmem>>>();

    dim3 g_proj(BDIM/128, MTOT/256);    // (8, 16)
    gemm_h<1><<<g_proj, 256, shmem>>>(proj_b, out, BDIM, BDIM);
}

// round 14
// speedup vs baseline: 1.0199x; 1.0189x over previous
#include <cuda_runtime.h>
#include <cuda_fp16.h>
#include <cstdint>

#define BDIM 1024
#define NH 16
#define HD 64
#define BB 2
#define SEQ 2048
#define MTOT (BB*SEQ)
#define QK_SCALE 0.1803368801111204f   // 0.125 * log2(e)

// scratch (device globals — allocation-guard safe). Referenced ONLY from
// device code (host-passing gives host shadow addrs — the R4/R5 bug).
__device__ __half g_Q [(long)BB*NH*SEQ*HD];     // Q pre-scaled by QK_SCALE
__device__ __half g_K [(long)BB*NH*SEQ*HD];
__device__ __half g_Vt[(long)BB*NH*HD*SEQ];     // V transposed: [b,h,d,n]
__device__ __half g_O [(long)MTOT*BDIM];        // attention out, head-concat
__device__ __half g_Xh[(long)MTOT*BDIM];
__device__ __half g_Wh[(long)3*BDIM*BDIM];
__device__ __half g_PWh[(long)BDIM*BDIM];

// ---------------------------------------------------------------------------
// helpers
// ---------------------------------------------------------------------------
__device__ __forceinline__ float ex2f(float x) {
    float y;
    asm("ex2.approx.ftz.f32 %0, %1;" : "=f"(y) : "f"(x));
    return y;
}
__device__ __forceinline__ uint32_t smem_u32(const void* p) {
    uint32_t a;
    asm("{ .reg .u64 t; cvta.to.shared.u64 t, %1; cvt.u32.u64 %0, t; }" : "=r"(a) : "l"(p));
    return a;
}
__device__ __forceinline__ void cp16(uint32_t dst, const void* src) {
    asm volatile("cp.async.cg.shared.global [%0], [%1], 16;" :: "r"(dst), "l"(src) : "memory");
}
__device__ __forceinline__ uint32_t packh2(float lo, float hi) {
    __half2 h = __floats2half2_rn(lo, hi);
    return *(uint32_t*)&h;
}
__device__ __forceinline__ void ldsm4(uint32_t* r, uint32_t addr) {
    asm volatile("ldmatrix.sync.aligned.m8n8.x4.shared.b16 {%0,%1,%2,%3}, [%4];"
                 : "=r"(r[0]), "=r"(r[1]), "=r"(r[2]), "=r"(r[3]) : "r"(addr));
}
// mma.sync m16n8k16 f16 -> f32
__device__ __forceinline__ void mma_f16(float c[4],
                                        uint32_t a0, uint32_t a1, uint32_t a2, uint32_t a3,
                                        uint32_t b0, uint32_t b1) {
    asm volatile(
        "mma.sync.aligned.m16n8k16.row.col.f32.f16.f16.f32 "
        "{%0,%1,%2,%3}, {%4,%5,%6,%7}, {%8,%9}, {%0,%1,%2,%3};"
        : "+f"(c[0]), "+f"(c[1]), "+f"(c[2]), "+f"(c[3])
        : "r"(a0), "r"(a1), "r"(a2), "r"(a3), "r"(b0), "r"(b1));
}
// mma.sync m16n8k16 f16 -> f16 (2x rate; C/D = 2 regs of half2)
__device__ __forceinline__ void mma_f16h(uint32_t c[2],
                                         uint32_t a0, uint32_t a1, uint32_t a2, uint32_t a3,
                                         uint32_t b0, uint32_t b1) {
    asm volatile(
        "mma.sync.aligned.m16n8k16.row.col.f16.f16.f16.f16 "
        "{%0,%1}, {%2,%3,%4,%5}, {%6,%7}, {%0,%1};"
        : "+r"(c[0]), "+r"(c[1])
        : "r"(a0), "r"(a1), "r"(a2), "r"(a3), "r"(b0), "r"(b1));
}

// ---------------------------------------------------------------------------
// prepass: fp32 -> fp16 copies of x, qkv_w, proj_w
// ---------------------------------------------------------------------------
__global__ void half_prep(const float* __restrict__ x, const float* __restrict__ w,
                          const float* __restrict__ pw)
{
    int y = blockIdx.y;
    const float4* src;
    uint2* dst;
    long n4;
    if (y == 0)      { src = (const float4*)x;  dst = (uint2*)g_Xh;  n4 = (long)MTOT*BDIM/4; }
    else if (y == 1) { src = (const float4*)w;  dst = (uint2*)g_Wh;  n4 = (long)3*BDIM*BDIM/4; }
    else             { src = (const float4*)pw; dst = (uint2*)g_PWh; n4 = (long)BDIM*BDIM/4; }
    long stride = (long)gridDim.x * blockDim.x;
    for (long i = (long)blockIdx.x*blockDim.x + threadIdx.x; i < n4; i += stride) {
        float4 v = src[i];
        uint2 u;
        u.x = packh2(v.x, v.y);
        u.y = packh2(v.z, v.w);
        dst[i] = u;
    }
}

// ---------------------------------------------------------------------------
// FP16 GEMM — R9 configuration verbatim (proven best): block 128x128,
// Ktile 64, 256 thr, warp tile 64x32, ldmatrix + cp.async 3-stage, SW128.
// ---------------------------------------------------------------------------
#define STG_OP 16384             // 128 rows x 128B
#define STG    32768
#define NST    3                 // 96 KB

template<int MODE>
__global__ __launch_bounds__(256, 2)
void gemm_h(const float* __restrict__ bias, float* __restrict__ Cout,
            int K, int Nout)
{
    extern __shared__ char smem[];
    uint32_t sbase = smem_u32(smem);
    const __half* Ab = (MODE == 1) ? (const __half*)g_O  : (const __half*)g_Xh;
    const __half* Wb = (MODE == 1) ? (const __half*)g_PWh : (const __half*)g_Wh;

    int tid = threadIdx.x, warp = tid >> 5, lane = tid & 31;
    int g = lane >> 2, t = lane & 3;
    int wm = (warp >> 2) * 64, wn = (warp & 3) * 32;
    int m0 = blockIdx.y * 128, n0 = blockIdx.x * 128;

    const __half* asrc[4];
    const __half* bsrc[4];
    uint32_t doff[4];
    #pragma unroll
    for (int i = 0; i < 4; i++) {
        int cid = i*256 + tid;
        int row = cid >> 3, ch = cid & 7;
        doff[i] = (uint32_t)(row*128 + ((ch ^ (row & 7)) << 4));
        asrc[i] = Ab + (long)(m0 + row)*K + ch*8;
        bsrc[i] = Wb + (long)(n0 + row)*K + ch*8;
    }

    int lr16 = lane & 15;
    uint32_t hs = (uint32_t)(lane >> 4);
    uint32_t cx = (uint32_t)(lane & 7);
    uint32_t ar128[4], br128[2];
    #pragma unroll
    for (int mt = 0; mt < 4; mt++) ar128[mt] = (uint32_t)(wm + mt*16 + lr16) * 128u;
    #pragma unroll
    for (int p = 0; p < 2; p++)    br128[p] = (uint32_t)(wn + p*16 + lr16) * 128u;

    float acc[4][4][4];
    #pragma unroll
    for (int i = 0; i < 4; i++)
        #pragma unroll
        for (int j = 0; j < 4; j++)
            #pragma unroll
            for (int c = 0; c < 4; c++) acc[i][j][c] = 0.f;

    int niter = K >> 6;

    #pragma unroll
    for (int s = 0; s < 2; s++) {
        uint32_t db = sbase + s*STG;
        #pragma unroll
        for (int i = 0; i < 4; i++) {
            cp16(db + doff[i],          asrc[i] + s*64);
            cp16(db + STG_OP + doff[i], bsrc[i] + s*64);
        }
        asm volatile("cp.async.commit_group;" ::: "memory");
    }

    for (int it = 0; it < niter; ++it) {
        asm volatile("cp.async.wait_group 1;" ::: "memory");
        __syncthreads();

        int nx = it + 2;
        if (nx < niter) {
            uint32_t db = sbase + (nx % NST)*STG;
            long koff = (long)nx * 64;
            #pragma unroll
            for (int i = 0; i < 4; i++) {
                cp16(db + doff[i],          asrc[i] + koff);
                cp16(db + STG_OP + doff[i], bsrc[i] + koff);
            }
        }
        asm volatile("cp.async.commit_group;" ::: "memory");

        uint32_t sA = sbase + (it % NST)*STG;
        uint32_t sB = sA + STG_OP;

        #pragma unroll
        for (int kk = 0; kk < 4; kk++) {
            uint32_t sw = ((2u*kk + hs) ^ cx) << 4;
            uint32_t af[4][4], bf[2][4];
            #pragma unroll
            for (int mt = 0; mt < 4; mt++) ldsm4(af[mt], sA + ar128[mt] + sw);
            #pragma unroll
            for (int p = 0; p < 2; p++)    ldsm4(bf[p], sB + br128[p] + sw);
            #pragma unroll
            for (int mt = 0; mt < 4; mt++) {
                #pragma unroll
                for (int p = 0; p < 2; p++) {
                    mma_f16(acc[mt][2*p],   af[mt][0], af[mt][1], af[mt][2], af[mt][3],
                            bf[p][0], bf[p][2]);
                    mma_f16(acc[mt][2*p+1], af[mt][0], af[mt][1], af[mt][2], af[mt][3],
                            bf[p][1], bf[p][3]);
                }
            }
        }
    }

    #pragma unroll
    for (int mt = 0; mt < 4; mt++) {
        int rowA = m0 + wm + mt*16 + g;
        int rowB = rowA + 8;
        #pragma unroll
        for (int nt = 0; nt < 4; nt++) {
            int col = n0 + wn + nt*8 + 2*t;
            float b0v = bias[col], b1v = bias[col+1];
            float2 va = make_float2(acc[mt][nt][0] + b0v, acc[mt][nt][1] + b1v);
            float2 vb = make_float2(acc[mt][nt][2] + b0v, acc[mt][nt][3] + b1v);
            if (MODE == 0) {
                int which = col >> 10;
                int c = col & (BDIM - 1);
                int hh = c >> 6, d = c & 63;
                int bA = rowA >> 11, nA = rowA & (SEQ - 1);
                int bR = rowB >> 11, nR = rowB & (SEQ - 1);
                if (which == 0) {
                    va.x *= QK_SCALE; va.y *= QK_SCALE;
                    vb.x *= QK_SCALE; vb.y *= QK_SCALE;
                    *(uint32_t*)(g_Q + ((((long)bA*NH + hh)*SEQ) + nA)*HD + d) = packh2(va.x, va.y);
                    *(uint32_t*)(g_Q + ((((long)bR*NH + hh)*SEQ) + nR)*HD + d) = packh2(vb.x, vb.y);
                } else if (which == 1) {
                    *(uint32_t*)(g_K + ((((long)bA*NH + hh)*SEQ) + nA)*HD + d) = packh2(va.x, va.y);
                    *(uint32_t*)(g_K + ((((long)bR*NH + hh)*SEQ) + nR)*HD + d) = packh2(vb.x, vb.y);
                } else {                 // V transposed: [b,h,d,n]
                    __half* vt = g_Vt;
                    long baseA = (((long)bA*NH + hh)*HD);
                    long baseB = (((long)bR*NH + hh)*HD);
                    vt[(baseA + d  )*SEQ + nA] = __float2half_rn(va.x);
                    vt[(baseA + d+1)*SEQ + nA] = __float2half_rn(va.y);
                    vt[(baseB + d  )*SEQ + nR] = __float2half_rn(vb.x);
                    vt[(baseB + d+1)*SEQ + nR] = __float2half_rn(vb.y);
                }
            } else {
                *(float2*)(Cout + (long)rowA * Nout + col) = va;
                *(float2*)(Cout + (long)rowB * Nout + col) = vb;
            }
        }
    }
}

// ---------------------------------------------------------------------------
// FP16 flash attention (R9 structure) with QK in f16-accumulate MMA (2x rate;
// K=64 = single chunk so no spill). The f16 C-fragment of S is DIRECTLY the
// PV A-fragment after the softmax exp (reg0 = row g cols 2t/2t+1, reg1 =
// row g+8) — softmax unpacks to f32, computes p, repacks in place.
// PV stays f32-accumulate. 8 warps x 32 q-rows, 64-key tiles, SW128,
// ldmatrix, cp.async 3-stage.
// ---------------------------------------------------------------------------
#define KBY 8192                     // 64 rows x 128B
#define ABUF (2*KBY)
#define ANST 3                       // 48 KB

__global__ __launch_bounds__(256, 1)
void attn_h()
{
    extern __shared__ __align__(16) char dsm[];

    int tid  = threadIdx.x;
    int lane = tid & 31, warp = tid >> 5;      // warp 0..7
    int g = lane >> 2, t = lane & 3;
    int b = blockIdx.z, h = blockIdx.y;
    const __half* Qb  = g_Q  + ((long)(b*NH + h)) * SEQ * HD;
    const __half* Kb  = g_K  + ((long)(b*NH + h)) * SEQ * HD;
    const __half* Vtb = g_Vt + ((long)(b*NH + h)) * HD * SEQ;

    int qn = blockIdx.x * 256 + warp * 32;

    uint32_t sb = smem_u32(dsm);
    uint32_t kdo[2];
    const __half* ksrc[2];
    const __half* vsrc[2];
    #pragma unroll
    for (int i = 0; i < 2; i++) {
        int cid = i*256 + tid;
        int row = cid >> 3, ch = cid & 7;          // row 0..63
        kdo[i] = (uint32_t)(row*128 + ((ch ^ (row & 7)) << 4));
        ksrc[i] = Kb  + (long)row*HD  + ch*8;      // +64*HD per tile
        vsrc[i] = Vtb + (long)row*SEQ + ch*8;      // +64 per tile
    }

    int lr16 = lane & 15;
    uint32_t hs = (uint32_t)(lane >> 4);
    uint32_t cx = (uint32_t)(lane & 7);
    uint32_t r128[4];
    #pragma unroll
    for (int p = 0; p < 4; p++) r128[p] = (uint32_t)(p*16 + lr16) * 128u;

    uint32_t qf[4][2][4];
    #pragma unroll
    for (int mt = 0; mt < 2; mt++) {
        const uint32_t* q0 = (const uint32_t*)(Qb + (long)(qn + mt*16 + g) * HD);
        const uint32_t* q1 = (const uint32_t*)(Qb + (long)(qn + mt*16 + g + 8) * HD);
        #pragma unroll
        for (int kk = 0; kk < 4; kk++) {
            qf[kk][mt][0] = q0[kk*8 + t];
            qf[kk][mt][1] = q1[kk*8 + t];
            qf[kk][mt][2] = q0[kk*8 + t + 4];
            qf[kk][mt][3] = q1[kk*8 + t + 4];
        }
    }

    float oacc[2][8][4];
    #pragma unroll
    for (int mt = 0; mt < 2; mt++)
        #pragma unroll
        for (int i = 0; i < 8; i++)
            #pragma unroll
            for (int j = 0; j < 4; j++) oacc[mt][i][j] = 0.f;
    float mA[2] = {-1e30f, -1e30f}, mB[2] = {-1e30f, -1e30f};
    float lA[2] = {0.f, 0.f},       lB[2] = {0.f, 0.f};

    #pragma unroll
    for (int s = 0; s < 2; s++) {
        uint32_t so = (uint32_t)s * ABUF;
        #pragma unroll
        for (int i = 0; i < 2; i++) {
            cp16(sb + so + kdo[i],       ksrc[i] + (long)s*64*HD);
            cp16(sb + so + KBY + kdo[i], vsrc[i] + s*64);
        }
        asm volatile("cp.async.commit_group;" ::: "memory");
    }

    const int NT = SEQ/64;
    for (int kt = 0; kt < NT; ++kt) {
        asm volatile("cp.async.wait_group 1;" ::: "memory");
        __syncthreads();

        if (kt + 2 < NT) {
            uint32_t so = (uint32_t)((kt+2) % ANST) * ABUF;
            #pragma unroll
            for (int i = 0; i < 2; i++) {
                cp16(sb + so + kdo[i],       ksrc[i] + (long)(kt+2)*64*HD);
                cp16(sb + so + KBY + kdo[i], vsrc[i] + (kt+2)*64);
            }
        }
        asm volatile("cp.async.commit_group;" ::: "memory");

        uint32_t sK = sb + (kt % ANST)*ABUF;
        uint32_t sV = sK + KBY;

        // S = Q @ K^T (log2 units), f16 accumulate (single K=64 chunk)
        uint32_t sch[2][8][2];
        #pragma unroll
        for (int mt = 0; mt < 2; mt++)
            #pragma unroll
            for (int i = 0; i < 8; i++) { sch[mt][i][0] = 0u; sch[mt][i][1] = 0u; }
        #pragma unroll
        for (int kk = 0; kk < 4; kk++) {
            uint32_t sw = ((2u*kk + hs) ^ cx) << 4;
            uint32_t kb[4][4];
            #pragma unroll
            for (int p = 0; p < 4; p++) ldsm4(kb[p], sK + r128[p] + sw);
            #pragma unroll
            for (int p = 0; p < 4; p++) {
                #pragma unroll
                for (int mt = 0; mt < 2; mt++) {
                    mma_f16h(sch[mt][2*p],   qf[kk][mt][0], qf[kk][mt][1], qf[kk][mt][2], qf[kk][mt][3],
                             kb[p][0], kb[p][2]);
                    mma_f16h(sch[mt][2*p+1], qf[kk][mt][0], qf[kk][mt][1], qf[kk][mt][2], qf[kk][mt][3],
                             kb[p][1], kb[p][3]);
                }
            }
        }

        // online softmax per m-tile: unpack f16 S -> f32, exp, repack as P
        #pragma unroll
        for (int mt = 0; mt < 2; mt++) {
            float s0[8], s1[8], s2[8], s3[8];
            #pragma unroll
            for (int nt = 0; nt < 8; nt++) {
                float2 lo = __half22float2(*(__half2*)&sch[mt][nt][0]);
                float2 hi = __half22float2(*(__half2*)&sch[mt][nt][1]);
                s0[nt] = lo.x; s1[nt] = lo.y;      // row g,   cols 2t, 2t+1
                s2[nt] = hi.x; s3[nt] = hi.y;      // row g+8, cols 2t, 2t+1
            }
            float mlA = -1e30f, mlB = -1e30f;
            #pragma unroll
            for (int nt = 0; nt < 8; nt++) {
                mlA = fmaxf(mlA, fmaxf(s0[nt], s1[nt]));
                mlB = fmaxf(mlB, fmaxf(s2[nt], s3[nt]));
            }
            mlA = fmaxf(mlA, __shfl_xor_sync(0xffffffffu, mlA, 1));
            mlA = fmaxf(mlA, __shfl_xor_sync(0xffffffffu, mlA, 2));
            mlB = fmaxf(mlB, __shfl_xor_sync(0xffffffffu, mlB, 1));
            mlB = fmaxf(mlB, __shfl_xor_sync(0xffffffffu, mlB, 2));
            float mnA = fmaxf(mA[mt], mlA), mnB = fmaxf(mB[mt], mlB);
            float cA = ex2f(mA[mt] - mnA), cB = ex2f(mB[mt] - mnB);
            lA[mt] *= cA; lB[mt] *= cB;
            #pragma unroll
            for (int nt = 0; nt < 8; nt++) {
                oacc[mt][nt][0] *= cA; oacc[mt][nt][1] *= cA;
                oacc[mt][nt][2] *= cB; oacc[mt][nt][3] *= cB;
            }
            #pragma unroll
            for (int nt = 0; nt < 8; nt++) {
                float p0 = ex2f(s0[nt] - mnA);
                float p1 = ex2f(s1[nt] - mnA);
                float p2 = ex2f(s2[nt] - mnB);
                float p3 = ex2f(s3[nt] - mnB);
                lA[mt] += p0 + p1; lB[mt] += p2 + p3;
                sch[mt][nt][0] = packh2(p0, p1);   // row g   -> A-frag reg0
                sch[mt][nt][1] = packh2(p2, p3);   // row g+8 -> A-frag reg1
            }
            mA[mt] = mnA; mB[mt] = mnB;
        }

        // O += P @ V : sch IS the PV A-frag (f16 C == A identity), f32 accum
        #pragma unroll
        for (int kk = 0; kk < 4; kk++) {
            uint32_t sw = ((2u*kk + hs) ^ cx) << 4;
            uint32_t vb[4][4];
            #pragma unroll
            for (int p = 0; p < 4; p++) ldsm4(vb[p], sV + r128[p] + sw);
            #pragma unroll
            for (int p = 0; p < 4; p++) {
                #pragma unroll
                for (int mt = 0; mt < 2; mt++) {
                    mma_f16(oacc[mt][2*p],
                            sch[mt][2*kk][0], sch[mt][2*kk][1], sch[mt][2*kk+1][0], sch[mt][2*kk+1][1],
                            vb[p][0], vb[p][2]);
                    mma_f16(oacc[mt][2*p+1],
                            sch[mt][2*kk][0], sch[mt][2*kk][1], sch[mt][2*kk+1][0], sch[mt][2*kk+1][1],
                            vb[p][1], vb[p][3]);
                }
            }
        }
    }

    // finalize
    #pragma unroll
    for (int mt = 0; mt < 2; mt++) {
        float la = lA[mt], lb = lB[mt];
        la += __shfl_xor_sync(0xffffffffu, la, 1);
        la += __shfl_xor_sync(0xffffffffu, la, 2);
        lb += __shfl_xor_sync(0xffffffffu, lb, 1);
        lb += __shfl_xor_sync(0xffffffffu, lb, 2);
        float iA = 1.f / la, iB = 1.f / lb;

        __half* OA = g_O + ((long)(b*SEQ) + qn + mt*16 + g) * BDIM + h*HD;
        __half* OB = OA + 8*BDIM;
        #pragma unroll
        for (int nt = 0; nt < 8; nt++) {
            int c = nt*8 + 2*t;
            *(uint32_t*)(OA + c) = packh2(oacc[mt][nt][0]*iA, oacc[mt][nt][1]*iA);
            *(uint32_t*)(OB + c) = packh2(oacc[mt][nt][2]*iB, oacc[mt][nt][3]*iB);
        }
    }
}

// ---------------------------------------------------------------------------
extern "C" void kernel_launch(void* const* d_in, const int* in_sizes, int n_in,
                              void* d_out, int out_size)
{
    const float* x      = (const float*)d_in[0];
    const float* qkv_w  = (const float*)d_in[1];
    const float* qkv_b  = (const float*)d_in[2];
    const float* proj_w = (const float*)d_in[3];
    const float* proj_b = (const float*)d_in[4];
    float* out = (float*)d_out;

    int shmem  = NST * STG;      // 98304
    int ashmem = ANST * ABUF;    // 49152
    cudaFuncSetAttribute(gemm_h<0>, cudaFuncAttributeMaxDynamicSharedMemorySize, shmem);
    cudaFuncSetAttribute(gemm_h<1>, cudaFuncAttributeMaxDynamicSharedMemorySize, shmem);
    cudaFuncSetAttribute(attn_h, cudaFuncAttributeMaxDynamicSharedMemorySize, ashmem);

    half_prep<<<dim3(1024, 3), 256>>>(x, qkv_w, proj_w);

    dim3 g_qkv(3*BDIM/128, MTOT/128);   // (24, 32)
    gemm_h<0><<<g_qkv, 256, shmem>>>(qkv_b, nullptr, BDIM, 3*BDIM);

    dim3 g_attn(SEQ/256, NH, BB);       // (8, 16, 2)
    attn_h<<<g_attn, 256, ashmem>>>();

    dim3 g_proj(BDIM/128, MTOT/128);    // (8, 32)
    gemm_h<1><<<g_proj, 256, shmem>>>(proj_b, out, BDIM, BDIM);
}

// round 15
// speedup vs baseline: 1.0252x; 1.0052x over previous
#include <cuda_runtime.h>
#include <cuda_fp16.h>
#include <cstdint>

#define BDIM 1024
#define NH 16
#define HD 64
#define BB 2
#define SEQ 2048
#define MTOT (BB*SEQ)
#define QK_SCALE 0.1803368801111204f   // 0.125 * log2(e)

// scratch (device globals — allocation-guard safe). Referenced ONLY from
// device code (host-passing gives host shadow addrs — the R4/R5 bug).
__device__ __half g_Q [(long)BB*NH*SEQ*HD];     // Q pre-scaled by QK_SCALE
__device__ __half g_K [(long)BB*NH*SEQ*HD];
__device__ __half g_Vt[(long)BB*NH*HD*SEQ];     // V transposed: [b,h,d,n]
__device__ __half g_O [(long)MTOT*BDIM];        // attention out, head-concat
__device__ __half g_Xh[(long)MTOT*BDIM];
__device__ __half g_Wh[(long)3*BDIM*BDIM];
__device__ __half g_PWh[(long)BDIM*BDIM];

// ---------------------------------------------------------------------------
// helpers
// ---------------------------------------------------------------------------
__device__ __forceinline__ float ex2f(float x) {
    float y;
    asm("ex2.approx.ftz.f32 %0, %1;" : "=f"(y) : "f"(x));
    return y;
}
__device__ __forceinline__ uint32_t smem_u32(const void* p) {
    uint32_t a;
    asm("{ .reg .u64 t; cvta.to.shared.u64 t, %1; cvt.u32.u64 %0, t; }" : "=r"(a) : "l"(p));
    return a;
}
__device__ __forceinline__ void cp16(uint32_t dst, const void* src) {
    asm volatile("cp.async.cg.shared.global [%0], [%1], 16;" :: "r"(dst), "l"(src) : "memory");
}
__device__ __forceinline__ uint32_t packh2(float lo, float hi) {
    __half2 h = __floats2half2_rn(lo, hi);
    return *(uint32_t*)&h;
}
__device__ __forceinline__ void ldsm4(uint32_t* r, uint32_t addr) {
    asm volatile("ldmatrix.sync.aligned.m8n8.x4.shared.b16 {%0,%1,%2,%3}, [%4];"
                 : "=r"(r[0]), "=r"(r[1]), "=r"(r[2]), "=r"(r[3]) : "r"(addr));
}
// mma.sync m16n8k16 f16 -> f32
__device__ __forceinline__ void mma_f16(float c[4],
                                        uint32_t a0, uint32_t a1, uint32_t a2, uint32_t a3,
                                        uint32_t b0, uint32_t b1) {
    asm volatile(
        "mma.sync.aligned.m16n8k16.row.col.f32.f16.f16.f32 "
        "{%0,%1,%2,%3}, {%4,%5,%6,%7}, {%8,%9}, {%0,%1,%2,%3};"
        : "+f"(c[0]), "+f"(c[1]), "+f"(c[2]), "+f"(c[3])
        : "r"(a0), "r"(a1), "r"(a2), "r"(a3), "r"(b0), "r"(b1));
}

// ---------------------------------------------------------------------------
// prepass: fp32 -> fp16 copies of x, qkv_w, proj_w
// ---------------------------------------------------------------------------
__global__ void half_prep(const float* __restrict__ x, const float* __restrict__ w,
                          const float* __restrict__ pw)
{
    int y = blockIdx.y;
    const float4* src;
    uint2* dst;
    long n4;
    if (y == 0)      { src = (const float4*)x;  dst = (uint2*)g_Xh;  n4 = (long)MTOT*BDIM/4; }
    else if (y == 1) { src = (const float4*)w;  dst = (uint2*)g_Wh;  n4 = (long)3*BDIM*BDIM/4; }
    else             { src = (const float4*)pw; dst = (uint2*)g_PWh; n4 = (long)BDIM*BDIM/4; }
    long stride = (long)gridDim.x * blockDim.x;
    for (long i = (long)blockIdx.x*blockDim.x + threadIdx.x; i < n4; i += stride) {
        float4 v = src[i];
        uint2 u;
        u.x = packh2(v.x, v.y);
        u.y = packh2(v.z, v.w);
        dst[i] = u;
    }
}

// ---------------------------------------------------------------------------
// FP16 GEMM v4: CTA 128x128, FOUR warps (128 thr) with 64x64 warp tiles —
// ldsm:MMA ratio 0.25 (matches the attention kernel's measured-faster shape).
// mma.sync m16n8k16 + ldmatrix + cp.async 3-stage, SW128 smem, 2 CTAs/SM.
//   MODE 0: A=g_Xh, W=g_Wh,  epilogue -> half Q(scaled)/K/[Vt transposed]
//   MODE 1: A=g_O,  W=g_PWh, epilogue -> fp32 row-major C
// ---------------------------------------------------------------------------
#define STG_OP 16384             // 128 rows x 128B
#define STG    32768
#define NST    3                 // 96 KB

template<int MODE>
__global__ __launch_bounds__(128, 2)
void gemm_h(const float* __restrict__ bias, float* __restrict__ Cout,
            int K, int Nout)
{
    extern __shared__ char smem[];
    uint32_t sbase = smem_u32(smem);
    const __half* Ab = (MODE == 1) ? (const __half*)g_O  : (const __half*)g_Xh;
    const __half* Wb = (MODE == 1) ? (const __half*)g_PWh : (const __half*)g_Wh;

    int tid = threadIdx.x, warp = tid >> 5, lane = tid & 31;
    int g = lane >> 2, t = lane & 3;
    int wm = (warp >> 1) * 64, wn = (warp & 1) * 64;
    int m0 = blockIdx.y * 128, n0 = blockIdx.x * 128;

    // cp.async: 8 A-chunks + 8 B-chunks (16B) per thread per stage
    const __half* asrc[8];
    const __half* bsrc[8];
    uint32_t doff[8];
    #pragma unroll
    for (int i = 0; i < 8; i++) {
        int cid = i*128 + tid;              // 0..1023
        int row = cid >> 3, ch = cid & 7;
        doff[i] = (uint32_t)(row*128 + ((ch ^ (row & 7)) << 4));
        asrc[i] = Ab + (long)(m0 + row)*K + ch*8;
        bsrc[i] = Wb + (long)(n0 + row)*K + ch*8;
    }

    // ldmatrix lane addressing
    int lr16 = lane & 15;
    uint32_t hs = (uint32_t)(lane >> 4);
    uint32_t cx = (uint32_t)(lane & 7);
    uint32_t ar128[4], br128[4];
    #pragma unroll
    for (int mt = 0; mt < 4; mt++) ar128[mt] = (uint32_t)(wm + mt*16 + lr16) * 128u;
    #pragma unroll
    for (int p = 0; p < 4; p++)    br128[p] = (uint32_t)(wn + p*16 + lr16) * 128u;

    float acc[4][8][4];
    #pragma unroll
    for (int i = 0; i < 4; i++)
        #pragma unroll
        for (int j = 0; j < 8; j++)
            #pragma unroll
            for (int c = 0; c < 4; c++) acc[i][j][c] = 0.f;

    int niter = K >> 6;

    #pragma unroll
    for (int s = 0; s < 2; s++) {
        uint32_t db = sbase + s*STG;
        #pragma unroll
        for (int i = 0; i < 8; i++) {
            cp16(db + doff[i],          asrc[i] + s*64);
            cp16(db + STG_OP + doff[i], bsrc[i] + s*64);
        }
        asm volatile("cp.async.commit_group;" ::: "memory");
    }

    for (int it = 0; it < niter; ++it) {
        asm volatile("cp.async.wait_group 1;" ::: "memory");
        __syncthreads();

        int nx = it + 2;
        if (nx < niter) {
            uint32_t db = sbase + (nx % NST)*STG;
            long koff = (long)nx * 64;
            #pragma unroll
            for (int i = 0; i < 8; i++) {
                cp16(db + doff[i],          asrc[i] + koff);
                cp16(db + STG_OP + doff[i], bsrc[i] + koff);
            }
        }
        asm volatile("cp.async.commit_group;" ::: "memory");

        uint32_t sA = sbase + (it % NST)*STG;
        uint32_t sB = sA + STG_OP;

        #pragma unroll
        for (int kk = 0; kk < 4; kk++) {
            uint32_t sw = ((2u*kk + hs) ^ cx) << 4;
            uint32_t af[4][4], bf[4][4];
            #pragma unroll
            for (int mt = 0; mt < 4; mt++) ldsm4(af[mt], sA + ar128[mt] + sw);
            #pragma unroll
            for (int p = 0; p < 4; p++)    ldsm4(bf[p], sB + br128[p] + sw);
            #pragma unroll
            for (int mt = 0; mt < 4; mt++) {
                #pragma unroll
                for (int p = 0; p < 4; p++) {
                    mma_f16(acc[mt][2*p],   af[mt][0], af[mt][1], af[mt][2], af[mt][3],
                            bf[p][0], bf[p][2]);
                    mma_f16(acc[mt][2*p+1], af[mt][0], af[mt][1], af[mt][2], af[mt][3],
                            bf[p][1], bf[p][3]);
                }
            }
        }
    }

    // epilogue
    #pragma unroll
    for (int mt = 0; mt < 4; mt++) {
        int rowA = m0 + wm + mt*16 + g;
        int rowB = rowA + 8;
        #pragma unroll
        for (int nt = 0; nt < 8; nt++) {
            int col = n0 + wn + nt*8 + 2*t;
            float b0v = bias[col], b1v = bias[col+1];
            float2 va = make_float2(acc[mt][nt][0] + b0v, acc[mt][nt][1] + b1v);
            float2 vb = make_float2(acc[mt][nt][2] + b0v, acc[mt][nt][3] + b1v);
            if (MODE == 0) {
                int which = col >> 10;
                int c = col & (BDIM - 1);
                int hh = c >> 6, d = c & 63;
                int bA = rowA >> 11, nA = rowA & (SEQ - 1);
                int bR = rowB >> 11, nR = rowB & (SEQ - 1);
                if (which == 0) {
                    va.x *= QK_SCALE; va.y *= QK_SCALE;
                    vb.x *= QK_SCALE; vb.y *= QK_SCALE;
                    *(uint32_t*)(g_Q + ((((long)bA*NH + hh)*SEQ) + nA)*HD + d) = packh2(va.x, va.y);
                    *(uint32_t*)(g_Q + ((((long)bR*NH + hh)*SEQ) + nR)*HD + d) = packh2(vb.x, vb.y);
                } else if (which == 1) {
                    *(uint32_t*)(g_K + ((((long)bA*NH + hh)*SEQ) + nA)*HD + d) = packh2(va.x, va.y);
                    *(uint32_t*)(g_K + ((((long)bR*NH + hh)*SEQ) + nR)*HD + d) = packh2(vb.x, vb.y);
                } else {                 // V transposed: [b,h,d,n]
                    __half* vt = g_Vt;
                    long baseA = (((long)bA*NH + hh)*HD);
                    long baseB = (((long)bR*NH + hh)*HD);
                    vt[(baseA + d  )*SEQ + nA] = __float2half_rn(va.x);
                    vt[(baseA + d+1)*SEQ + nA] = __float2half_rn(va.y);
                    vt[(baseB + d  )*SEQ + nR] = __float2half_rn(vb.x);
                    vt[(baseB + d+1)*SEQ + nR] = __float2half_rn(vb.y);
                }
            } else {
                *(float2*)(Cout + (long)rowA * Nout + col) = va;
                *(float2*)(Cout + (long)rowB * Nout + col) = vb;
            }
        }
    }
}

// ---------------------------------------------------------------------------
// FP16 flash attention — R9 configuration verbatim (proven best):
// 8 warps x 32 q-rows (256 q-rows/CTA), 64-key tiles, SW128 K/Vt smem,
// ldmatrix frags, cp.async 3-stage. S C-frag == PV A-frag identity.
// ---------------------------------------------------------------------------
#define KBY 8192                     // 64 rows x 128B
#define ABUF (2*KBY)
#define ANST 3                       // 48 KB

__global__ __launch_bounds__(256, 1)
void attn_h()
{
    extern __shared__ __align__(16) char dsm[];

    int tid  = threadIdx.x;
    int lane = tid & 31, warp = tid >> 5;      // warp 0..7
    int g = lane >> 2, t = lane & 3;
    int b = blockIdx.z, h = blockIdx.y;
    const __half* Qb  = g_Q  + ((long)(b*NH + h)) * SEQ * HD;
    const __half* Kb  = g_K  + ((long)(b*NH + h)) * SEQ * HD;
    const __half* Vtb = g_Vt + ((long)(b*NH + h)) * HD * SEQ;

    int qn = blockIdx.x * 256 + warp * 32;

    uint32_t sb = smem_u32(dsm);
    uint32_t kdo[2];
    const __half* ksrc[2];
    const __half* vsrc[2];
    #pragma unroll
    for (int i = 0; i < 2; i++) {
        int cid = i*256 + tid;
        int row = cid >> 3, ch = cid & 7;          // row 0..63
        kdo[i] = (uint32_t)(row*128 + ((ch ^ (row & 7)) << 4));
        ksrc[i] = Kb  + (long)row*HD  + ch*8;      // +64*HD per tile
        vsrc[i] = Vtb + (long)row*SEQ + ch*8;      // +64 per tile
    }

    int lr16 = lane & 15;
    uint32_t hs = (uint32_t)(lane >> 4);
    uint32_t cx = (uint32_t)(lane & 7);
    uint32_t r128[4];
    #pragma unroll
    for (int p = 0; p < 4; p++) r128[p] = (uint32_t)(p*16 + lr16) * 128u;

    uint32_t qf[4][2][4];
    #pragma unroll
    for (int mt = 0; mt < 2; mt++) {
        const uint32_t* q0 = (const uint32_t*)(Qb + (long)(qn + mt*16 + g) * HD);
        const uint32_t* q1 = (const uint32_t*)(Qb + (long)(qn + mt*16 + g + 8) * HD);
        #pragma unroll
        for (int kk = 0; kk < 4; kk++) {
            qf[kk][mt][0] = q0[kk*8 + t];
            qf[kk][mt][1] = q1[kk*8 + t];
            qf[kk][mt][2] = q0[kk*8 + t + 4];
            qf[kk][mt][3] = q1[kk*8 + t + 4];
        }
    }

    float oacc[2][8][4];
    #pragma unroll
    for (int mt = 0; mt < 2; mt++)
        #pragma unroll
        for (int i = 0; i < 8; i++)
            #pragma unroll
            for (int j = 0; j < 4; j++) oacc[mt][i][j] = 0.f;
    float mA[2] = {-1e30f, -1e30f}, mB[2] = {-1e30f, -1e30f};
    float lA[2] = {0.f, 0.f},       lB[2] = {0.f, 0.f};

    #pragma unroll
    for (int s = 0; s < 2; s++) {
        uint32_t so = (uint32_t)s * ABUF;
        #pragma unroll
        for (int i = 0; i < 2; i++) {
            cp16(sb + so + kdo[i],       ksrc[i] + (long)s*64*HD);
            cp16(sb + so + KBY + kdo[i], vsrc[i] + s*64);
        }
        asm volatile("cp.async.commit_group;" ::: "memory");
    }

    const int NT = SEQ/64;
    for (int kt = 0; kt < NT; ++kt) {
        asm volatile("cp.async.wait_group 1;" ::: "memory");
        __syncthreads();

        if (kt + 2 < NT) {
            uint32_t so = (uint32_t)((kt+2) % ANST) * ABUF;
            #pragma unroll
            for (int i = 0; i < 2; i++) {
                cp16(sb + so + kdo[i],       ksrc[i] + (long)(kt+2)*64*HD);
                cp16(sb + so + KBY + kdo[i], vsrc[i] + (kt+2)*64);
            }
        }
        asm volatile("cp.async.commit_group;" ::: "memory");

        uint32_t sK = sb + (kt % ANST)*ABUF;
        uint32_t sV = sK + KBY;

        // S = Q @ K^T (log2 units)
        float sc[2][8][4];
        #pragma unroll
        for (int mt = 0; mt < 2; mt++)
            #pragma unroll
            for (int i = 0; i < 8; i++)
                #pragma unroll
                for (int j = 0; j < 4; j++) sc[mt][i][j] = 0.f;
        #pragma unroll
        for (int kk = 0; kk < 4; kk++) {
            uint32_t sw = ((2u*kk + hs) ^ cx) << 4;
            uint32_t kb[4][4];
            #pragma unroll
            for (int p = 0; p < 4; p++) ldsm4(kb[p], sK + r128[p] + sw);
            #pragma unroll
            for (int p = 0; p < 4; p++) {
                #pragma unroll
                for (int mt = 0; mt < 2; mt++) {
                    mma_f16(sc[mt][2*p],   qf[kk][mt][0], qf[kk][mt][1], qf[kk][mt][2], qf[kk][mt][3],
                            kb[p][0], kb[p][2]);
                    mma_f16(sc[mt][2*p+1], qf[kk][mt][0], qf[kk][mt][1], qf[kk][mt][2], qf[kk][mt][3],
                            kb[p][1], kb[p][3]);
                }
            }
        }

        // online softmax per m-tile
        #pragma unroll
        for (int mt = 0; mt < 2; mt++) {
            float mlA = -1e30f, mlB = -1e30f;
            #pragma unroll
            for (int nt = 0; nt < 8; nt++) {
                mlA = fmaxf(mlA, fmaxf(sc[mt][nt][0], sc[mt][nt][1]));
                mlB = fmaxf(mlB, fmaxf(sc[mt][nt][2], sc[mt][nt][3]));
            }
            mlA = fmaxf(mlA, __shfl_xor_sync(0xffffffffu, mlA, 1));
            mlA = fmaxf(mlA, __shfl_xor_sync(0xffffffffu, mlA, 2));
            mlB = fmaxf(mlB, __shfl_xor_sync(0xffffffffu, mlB, 1));
            mlB = fmaxf(mlB, __shfl_xor_sync(0xffffffffu, mlB, 2));
            float mnA = fmaxf(mA[mt], mlA), mnB = fmaxf(mB[mt], mlB);
            float cA = ex2f(mA[mt] - mnA), cB = ex2f(mB[mt] - mnB);
            lA[mt] *= cA; lB[mt] *= cB;
            #pragma unroll
            for (int nt = 0; nt < 8; nt++) {
                oacc[mt][nt][0] *= cA; oacc[mt][nt][1] *= cA;
                oacc[mt][nt][2] *= cB; oacc[mt][nt][3] *= cB;
            }
            #pragma unroll
            for (int nt = 0; nt < 8; nt++) {
                float p0 = ex2f(sc[mt][nt][0] - mnA);
                float p1 = ex2f(sc[mt][nt][1] - mnA);
                float p2 = ex2f(sc[mt][nt][2] - mnB);
                float p3 = ex2f(sc[mt][nt][3] - mnB);
                lA[mt] += p0 + p1; lB[mt] += p2 + p3;
                sc[mt][nt][0] = p0; sc[mt][nt][1] = p1;
                sc[mt][nt][2] = p2; sc[mt][nt][3] = p3;
            }
            mA[mt] = mnA; mB[mt] = mnB;
        }

        // O += P @ V : S C-frag IS the PV A-frag; V frags via ldmatrix
        #pragma unroll
        for (int kk = 0; kk < 4; kk++) {
            uint32_t sw = ((2u*kk + hs) ^ cx) << 4;
            uint32_t Af[2][4];
            #pragma unroll
            for (int mt = 0; mt < 2; mt++) {
                Af[mt][0] = packh2(sc[mt][2*kk][0],   sc[mt][2*kk][1]);
                Af[mt][1] = packh2(sc[mt][2*kk][2],   sc[mt][2*kk][3]);
                Af[mt][2] = packh2(sc[mt][2*kk+1][0], sc[mt][2*kk+1][1]);
                Af[mt][3] = packh2(sc[mt][2*kk+1][2], sc[mt][2*kk+1][3]);
            }
            uint32_t vb[4][4];
            #pragma unroll
            for (int p = 0; p < 4; p++) ldsm4(vb[p], sV + r128[p] + sw);
            #pragma unroll
            for (int p = 0; p < 4; p++) {
                #pragma unroll
                for (int mt = 0; mt < 2; mt++) {
                    mma_f16(oacc[mt][2*p],   Af[mt][0], Af[mt][1], Af[mt][2], Af[mt][3],
                            vb[p][0], vb[p][2]);
                    mma_f16(oacc[mt][2*p+1], Af[mt][0], Af[mt][1], Af[mt][2], Af[mt][3],
                            vb[p][1], vb[p][3]);
                }
            }
        }
    }

    // finalize
    #pragma unroll
    for (int mt = 0; mt < 2; mt++) {
        float la = lA[mt], lb = lB[mt];
        la += __shfl_xor_sync(0xffffffffu, la, 1);
        la += __shfl_xor_sync(0xffffffffu, la, 2);
        lb += __shfl_xor_sync(0xffffffffu, lb, 1);
        lb += __shfl_xor_sync(0xffffffffu, lb, 2);
        float iA = 1.f / la, iB = 1.f / lb;

        __half* OA = g_O + ((long)(b*SEQ) + qn + mt*16 + g) * BDIM + h*HD;
        __half* OB = OA + 8*BDIM;
        #pragma unroll
        for (int nt = 0; nt < 8; nt++) {
            int c = nt*8 + 2*t;
            *(uint32_t*)(OA + c) = packh2(oacc[mt][nt][0]*iA, oacc[mt][nt][1]*iA);
            *(uint32_t*)(OB + c) = packh2(oacc[mt][nt][2]*iB, oacc[mt][nt][3]*iB);
        }
    }
}

// ---------------------------------------------------------------------------
extern "C" void kernel_launch(void* const* d_in, const int* in_sizes, int n_in,
                              void* d_out, int out_size)
{
    const float* x      = (const float*)d_in[0];
    const float* qkv_w  = (const float*)d_in[1];
    const float* qkv_b  = (const float*)d_in[2];
    const float* proj_w = (const float*)d_in[3];
    const float* proj_b = (const float*)d_in[4];
    float* out = (float*)d_out;

    int shmem  = NST * STG;      // 98304
    int ashmem = ANST * ABUF;    // 49152
    cudaFuncSetAttribute(gemm_h<0>, cudaFuncAttributeMaxDynamicSharedMemorySize, shmem);
    cudaFuncSetAttribute(gemm_h<1>, cudaFuncAttributeMaxDynamicSharedMemorySize, shmem);
    cudaFuncSetAttribute(attn_h, cudaFuncAttributeMaxDynamicSharedMemorySize, ashmem);

    half_prep<<<dim3(1024, 3), 256>>>(x, qkv_w, proj_w);

    dim3 g_qkv(3*BDIM/128, MTOT/128);   // (24, 32)
    gemm_h<0><<<g_qkv, 128, shmem>>>(qkv_b, nullptr, BDIM, 3*BDIM);

    dim3 g_attn(SEQ/256, NH, BB);       // (8, 16, 2)
    attn_h<<<g_attn, 256, ashmem>>>();

    dim3 g_proj(BDIM/128, MTOT/128);    // (8, 32)
    gemm_h<1><<<g_proj, 128, shmem>>>(proj_b, out, BDIM, BDIM);
}

// round 16
// speedup vs baseline: 1.0361x; 1.0106x over previous
#include <cuda_runtime.h>
#include <cuda_fp16.h>
#include <cstdint>

#define BDIM 1024
#define NH 16
#define HD 64
#define BB 2
#define SEQ 2048
#define MTOT (BB*SEQ)
#define QK_SCALE 0.1803368801111204f   // 0.125 * log2(e)

// scratch (device globals — allocation-guard safe). Referenced ONLY from
// device code (host-passing gives host shadow addrs — the R4/R5 bug).
__device__ __half g_Q [(long)BB*NH*SEQ*HD];     // Q pre-scaled by QK_SCALE
__device__ __half g_K [(long)BB*NH*SEQ*HD];
__device__ __half g_Vt[(long)BB*NH*HD*SEQ];     // V transposed: [b,h,d,n]
__device__ __half g_O [(long)MTOT*BDIM];        // attention out, head-concat
__device__ __half g_Xh[(long)MTOT*BDIM];
__device__ __half g_Wh[(long)3*BDIM*BDIM];
__device__ __half g_PWh[(long)BDIM*BDIM];

// ---------------------------------------------------------------------------
// helpers
// ---------------------------------------------------------------------------
__device__ __forceinline__ float ex2f(float x) {
    float y;
    asm("ex2.approx.ftz.f32 %0, %1;" : "=f"(y) : "f"(x));
    return y;
}
__device__ __forceinline__ uint32_t smem_u32(const void* p) {
    uint32_t a;
    asm("{ .reg .u64 t; cvta.to.shared.u64 t, %1; cvt.u32.u64 %0, t; }" : "=r"(a) : "l"(p));
    return a;
}
__device__ __forceinline__ void cp16(uint32_t dst, const void* src) {
    asm volatile("cp.async.cg.shared.global [%0], [%1], 16;" :: "r"(dst), "l"(src) : "memory");
}
__device__ __forceinline__ uint32_t packh2(float lo, float hi) {
    __half2 h = __floats2half2_rn(lo, hi);
    return *(uint32_t*)&h;
}
__device__ __forceinline__ void ldsm4(uint32_t* r, uint32_t addr) {
    asm volatile("ldmatrix.sync.aligned.m8n8.x4.shared.b16 {%0,%1,%2,%3}, [%4];"
                 : "=r"(r[0]), "=r"(r[1]), "=r"(r[2]), "=r"(r[3]) : "r"(addr));
}
// mma.sync m16n8k16 f16 -> f32
__device__ __forceinline__ void mma_f16(float c[4],
                                        uint32_t a0, uint32_t a1, uint32_t a2, uint32_t a3,
                                        uint32_t b0, uint32_t b1) {
    asm volatile(
        "mma.sync.aligned.m16n8k16.row.col.f32.f16.f16.f32 "
        "{%0,%1,%2,%3}, {%4,%5,%6,%7}, {%8,%9}, {%0,%1,%2,%3};"
        : "+f"(c[0]), "+f"(c[1]), "+f"(c[2]), "+f"(c[3])
        : "r"(a0), "r"(a1), "r"(a2), "r"(a3), "r"(b0), "r"(b1));
}

// ---------------------------------------------------------------------------
// prepass: fp32 -> fp16 copies of x, qkv_w, proj_w. Flat one-float4-per-
// thread mapping (no grid-stride loop, no per-iteration branching) —
// memory-shaped, ~8-9 us for 48 MB.
// ---------------------------------------------------------------------------
#define N4_X  ((long)MTOT*BDIM/4)          // 1048576
#define N4_W  ((long)3*BDIM*BDIM/4)        //  786432
#define N4_PW ((long)BDIM*BDIM/4)          //  262144
#define N4_TOT (N4_X + N4_W + N4_PW)       // 2097152

__global__ __launch_bounds__(256)
void half_prep(const float* __restrict__ x, const float* __restrict__ w,
               const float* __restrict__ pw)
{
    long i = (long)blockIdx.x*blockDim.x + threadIdx.x;
    const float4* src;
    uint2* dst;
    long off;
    if (i < N4_X)             { src = (const float4*)x;  dst = (uint2*)g_Xh;  off = i; }
    else if (i < N4_X + N4_W) { src = (const float4*)w;  dst = (uint2*)g_Wh;  off = i - N4_X; }
    else                      { src = (const float4*)pw; dst = (uint2*)g_PWh; off = i - N4_X - N4_W; }
    float4 v = src[off];
    uint2 u;
    u.x = packh2(v.x, v.y);
    u.y = packh2(v.z, v.w);
    dst[off] = u;
}

// ---------------------------------------------------------------------------
// FP16 GEMM — R9 configuration verbatim (proven best): block 128x128,
// Ktile 64, 256 thr (8 warps, warp tile 64x32), ldmatrix + cp.async 3-stage,
// SW128 smem, 2 CTAs/SM.
// ---------------------------------------------------------------------------
#define STG_OP 16384             // 128 rows x 128B
#define STG    32768
#define NST    3                 // 96 KB

template<int MODE>
__global__ __launch_bounds__(256, 2)
void gemm_h(const float* __restrict__ bias, float* __restrict__ Cout,
            int K, int Nout)
{
    extern __shared__ char smem[];
    uint32_t sbase = smem_u32(smem);
    const __half* Ab = (MODE == 1) ? (const __half*)g_O  : (const __half*)g_Xh;
    const __half* Wb = (MODE == 1) ? (const __half*)g_PWh : (const __half*)g_Wh;

    int tid = threadIdx.x, warp = tid >> 5, lane = tid & 31;
    int g = lane >> 2, t = lane & 3;
    int wm = (warp >> 2) * 64, wn = (warp & 3) * 32;
    int m0 = blockIdx.y * 128, n0 = blockIdx.x * 128;

    const __half* asrc[4];
    const __half* bsrc[4];
    uint32_t doff[4];
    #pragma unroll
    for (int i = 0; i < 4; i++) {
        int cid = i*256 + tid;
        int row = cid >> 3, ch = cid & 7;
        doff[i] = (uint32_t)(row*128 + ((ch ^ (row & 7)) << 4));
        asrc[i] = Ab + (long)(m0 + row)*K + ch*8;
        bsrc[i] = Wb + (long)(n0 + row)*K + ch*8;
    }

    int lr16 = lane & 15;
    uint32_t hs = (uint32_t)(lane >> 4);
    uint32_t cx = (uint32_t)(lane & 7);
    uint32_t ar128[4], br128[2];
    #pragma unroll
    for (int mt = 0; mt < 4; mt++) ar128[mt] = (uint32_t)(wm + mt*16 + lr16) * 128u;
    #pragma unroll
    for (int p = 0; p < 2; p++)    br128[p] = (uint32_t)(wn + p*16 + lr16) * 128u;

    float acc[4][4][4];
    #pragma unroll
    for (int i = 0; i < 4; i++)
        #pragma unroll
        for (int j = 0; j < 4; j++)
            #pragma unroll
            for (int c = 0; c < 4; c++) acc[i][j][c] = 0.f;

    int niter = K >> 6;

    #pragma unroll
    for (int s = 0; s < 2; s++) {
        uint32_t db = sbase + s*STG;
        #pragma unroll
        for (int i = 0; i < 4; i++) {
            cp16(db + doff[i],          asrc[i] + s*64);
            cp16(db + STG_OP + doff[i], bsrc[i] + s*64);
        }
        asm volatile("cp.async.commit_group;" ::: "memory");
    }

    for (int it = 0; it < niter; ++it) {
        asm volatile("cp.async.wait_group 1;" ::: "memory");
        __syncthreads();

        int nx = it + 2;
        if (nx < niter) {
            uint32_t db = sbase + (nx % NST)*STG;
            long koff = (long)nx * 64;
            #pragma unroll
            for (int i = 0; i < 4; i++) {
                cp16(db + doff[i],          asrc[i] + koff);
                cp16(db + STG_OP + doff[i], bsrc[i] + koff);
            }
        }
        asm volatile("cp.async.commit_group;" ::: "memory");

        uint32_t sA = sbase + (it % NST)*STG;
        uint32_t sB = sA + STG_OP;

        #pragma unroll
        for (int kk = 0; kk < 4; kk++) {
            uint32_t sw = ((2u*kk + hs) ^ cx) << 4;
            uint32_t af[4][4], bf[2][4];
            #pragma unroll
            for (int mt = 0; mt < 4; mt++) ldsm4(af[mt], sA + ar128[mt] + sw);
            #pragma unroll
            for (int p = 0; p < 2; p++)    ldsm4(bf[p], sB + br128[p] + sw);
            #pragma unroll
            for (int mt = 0; mt < 4; mt++) {
                #pragma unroll
                for (int p = 0; p < 2; p++) {
                    mma_f16(acc[mt][2*p],   af[mt][0], af[mt][1], af[mt][2], af[mt][3],
                            bf[p][0], bf[p][2]);
                    mma_f16(acc[mt][2*p+1], af[mt][0], af[mt][1], af[mt][2], af[mt][3],
                            bf[p][1], bf[p][3]);
                }
            }
        }
    }

    #pragma unroll
    for (int mt = 0; mt < 4; mt++) {
        int rowA = m0 + wm + mt*16 + g;
        int rowB = rowA + 8;
        #pragma unroll
        for (int nt = 0; nt < 4; nt++) {
            int col = n0 + wn + nt*8 + 2*t;
            float b0v = bias[col], b1v = bias[col+1];
            float2 va = make_float2(acc[mt][nt][0] + b0v, acc[mt][nt][1] + b1v);
            float2 vb = make_float2(acc[mt][nt][2] + b0v, acc[mt][nt][3] + b1v);
            if (MODE == 0) {
                int which = col >> 10;
                int c = col & (BDIM - 1);
                int hh = c >> 6, d = c & 63;
                int bA = rowA >> 11, nA = rowA & (SEQ - 1);
                int bR = rowB >> 11, nR = rowB & (SEQ - 1);
                if (which == 0) {
                    va.x *= QK_SCALE; va.y *= QK_SCALE;
                    vb.x *= QK_SCALE; vb.y *= QK_SCALE;
                    *(uint32_t*)(g_Q + ((((long)bA*NH + hh)*SEQ) + nA)*HD + d) = packh2(va.x, va.y);
                    *(uint32_t*)(g_Q + ((((long)bR*NH + hh)*SEQ) + nR)*HD + d) = packh2(vb.x, vb.y);
                } else if (which == 1) {
                    *(uint32_t*)(g_K + ((((long)bA*NH + hh)*SEQ) + nA)*HD + d) = packh2(va.x, va.y);
                    *(uint32_t*)(g_K + ((((long)bR*NH + hh)*SEQ) + nR)*HD + d) = packh2(vb.x, vb.y);
                } else {                 // V transposed: [b,h,d,n]
                    __half* vt = g_Vt;
                    long baseA = (((long)bA*NH + hh)*HD);
                    long baseB = (((long)bR*NH + hh)*HD);
                    vt[(baseA + d  )*SEQ + nA] = __float2half_rn(va.x);
                    vt[(baseA + d+1)*SEQ + nA] = __float2half_rn(va.y);
                    vt[(baseB + d  )*SEQ + nR] = __float2half_rn(vb.x);
                    vt[(baseB + d+1)*SEQ + nR] = __float2half_rn(vb.y);
                }
            } else {
                *(float2*)(Cout + (long)rowA * Nout + col) = va;
                *(float2*)(Cout + (long)rowB * Nout + col) = vb;
            }
        }
    }
}

// ---------------------------------------------------------------------------
// FP16 flash attention — R9 configuration verbatim (proven best):
// 8 warps x 32 q-rows (256 q-rows/CTA), 64-key tiles, SW128 K/Vt smem,
// ldmatrix frags, cp.async 3-stage. S C-frag == PV A-frag identity.
// ---------------------------------------------------------------------------
#define KBY 8192                     // 64 rows x 128B
#define ABUF (2*KBY)
#define ANST 3                       // 48 KB

__global__ __launch_bounds__(256, 1)
void attn_h()
{
    extern __shared__ __align__(16) char dsm[];

    int tid  = threadIdx.x;
    int lane = tid & 31, warp = tid >> 5;      // warp 0..7
    int g = lane >> 2, t = lane & 3;
    int b = blockIdx.z, h = blockIdx.y;
    const __half* Qb  = g_Q  + ((long)(b*NH + h)) * SEQ * HD;
    const __half* Kb  = g_K  + ((long)(b*NH + h)) * SEQ * HD;
    const __half* Vtb = g_Vt + ((long)(b*NH + h)) * HD * SEQ;

    int qn = blockIdx.x * 256 + warp * 32;

    uint32_t sb = smem_u32(dsm);
    uint32_t kdo[2];
    const __half* ksrc[2];
    const __half* vsrc[2];
    #pragma unroll
    for (int i = 0; i < 2; i++) {
        int cid = i*256 + tid;
        int row = cid >> 3, ch = cid & 7;          // row 0..63
        kdo[i] = (uint32_t)(row*128 + ((ch ^ (row & 7)) << 4));
        ksrc[i] = Kb  + (long)row*HD  + ch*8;      // +64*HD per tile
        vsrc[i] = Vtb + (long)row*SEQ + ch*8;      // +64 per tile
    }

    int lr16 = lane & 15;
    uint32_t hs = (uint32_t)(lane >> 4);
    uint32_t cx = (uint32_t)(lane & 7);
    uint32_t r128[4];
    #pragma unroll
    for (int p = 0; p < 4; p++) r128[p] = (uint32_t)(p*16 + lr16) * 128u;

    uint32_t qf[4][2][4];
    #pragma unroll
    for (int mt = 0; mt < 2; mt++) {
        const uint32_t* q0 = (const uint32_t*)(Qb + (long)(qn + mt*16 + g) * HD);
        const uint32_t* q1 = (const uint32_t*)(Qb + (long)(qn + mt*16 + g + 8) * HD);
        #pragma unroll
        for (int kk = 0; kk < 4; kk++) {
            qf[kk][mt][0] = q0[kk*8 + t];
            qf[kk][mt][1] = q1[kk*8 + t];
            qf[kk][mt][2] = q0[kk*8 + t + 4];
            qf[kk][mt][3] = q1[kk*8 + t + 4];
        }
    }

    float oacc[2][8][4];
    #pragma unroll
    for (int mt = 0; mt < 2; mt++)
        #pragma unroll
        for (int i = 0; i < 8; i++)
            #pragma unroll
            for (int j = 0; j < 4; j++) oacc[mt][i][j] = 0.f;
    float mA[2] = {-1e30f, -1e30f}, mB[2] = {-1e30f, -1e30f};
    float lA[2] = {0.f, 0.f},       lB[2] = {0.f, 0.f};

    #pragma unroll
    for (int s = 0; s < 2; s++) {
        uint32_t so = (uint32_t)s * ABUF;
        #pragma unroll
        for (int i = 0; i < 2; i++) {
            cp16(sb + so + kdo[i],       ksrc[i] + (long)s*64*HD);
            cp16(sb + so + KBY + kdo[i], vsrc[i] + s*64);
        }
        asm volatile("cp.async.commit_group;" ::: "memory");
    }

    const int NT = SEQ/64;
    for (int kt = 0; kt < NT; ++kt) {
        asm volatile("cp.async.wait_group 1;" ::: "memory");
        __syncthreads();

        if (kt + 2 < NT) {
            uint32_t so = (uint32_t)((kt+2) % ANST) * ABUF;
            #pragma unroll
            for (int i = 0; i < 2; i++) {
                cp16(sb + so + kdo[i],       ksrc[i] + (long)(kt+2)*64*HD);
                cp16(sb + so + KBY + kdo[i], vsrc[i] + (kt+2)*64);
            }
        }
        asm volatile("cp.async.commit_group;" ::: "memory");

        uint32_t sK = sb + (kt % ANST)*ABUF;
        uint32_t sV = sK + KBY;

        // S = Q @ K^T (log2 units)
        float sc[2][8][4];
        #pragma unroll
        for (int mt = 0; mt < 2; mt++)
            #pragma unroll
            for (int i = 0; i < 8; i++)
                #pragma unroll
                for (int j = 0; j < 4; j++) sc[mt][i][j] = 0.f;
        #pragma unroll
        for (int kk = 0; kk < 4; kk++) {
            uint32_t sw = ((2u*kk + hs) ^ cx) << 4;
            uint32_t kb[4][4];
            #pragma unroll
            for (int p = 0; p < 4; p++) ldsm4(kb[p], sK + r128[p] + sw);
            #pragma unroll
            for (int p = 0; p < 4; p++) {
                #pragma unroll
                for (int mt = 0; mt < 2; mt++) {
                    mma_f16(sc[mt][2*p],   qf[kk][mt][0], qf[kk][mt][1], qf[kk][mt][2], qf[kk][mt][3],
                            kb[p][0], kb[p][2]);
                    mma_f16(sc[mt][2*p+1], qf[kk][mt][0], qf[kk][mt][1], qf[kk][mt][2], qf[kk][mt][3],
                            kb[p][1], kb[p][3]);
                }
            }
        }

        // online softmax per m-tile
        #pragma unroll
        for (int mt = 0; mt < 2; mt++) {
            float mlA = -1e30f, mlB = -1e30f;
            #pragma unroll
            for (int nt = 0; nt < 8; nt++) {
                mlA = fmaxf(mlA, fmaxf(sc[mt][nt][0], sc[mt][nt][1]));
                mlB = fmaxf(mlB, fmaxf(sc[mt][nt][2], sc[mt][nt][3]));
            }
            mlA = fmaxf(mlA, __shfl_xor_sync(0xffffffffu, mlA, 1));
            mlA = fmaxf(mlA, __shfl_xor_sync(0xffffffffu, mlA, 2));
            mlB = fmaxf(mlB, __shfl_xor_sync(0xffffffffu, mlB, 1));
            mlB = fmaxf(mlB, __shfl_xor_sync(0xffffffffu, mlB, 2));
            float mnA = fmaxf(mA[mt], mlA), mnB = fmaxf(mB[mt], mlB);
            float cA = ex2f(mA[mt] - mnA), cB = ex2f(mB[mt] - mnB);
            lA[mt] *= cA; lB[mt] *= cB;
            #pragma unroll
            for (int nt = 0; nt < 8; nt++) {
                oacc[mt][nt][0] *= cA; oacc[mt][nt][1] *= cA;
                oacc[mt][nt][2] *= cB; oacc[mt][nt][3] *= cB;
            }
            #pragma unroll
            for (int nt = 0; nt < 8; nt++) {
                float p0 = ex2f(sc[mt][nt][0] - mnA);
                float p1 = ex2f(sc[mt][nt][1] - mnA);
                float p2 = ex2f(sc[mt][nt][2] - mnB);
                float p3 = ex2f(sc[mt][nt][3] - mnB);
                lA[mt] += p0 + p1; lB[mt] += p2 + p3;
                sc[mt][nt][0] = p0; sc[mt][nt][1] = p1;
                sc[mt][nt][2] = p2; sc[mt][nt][3] = p3;
            }
            mA[mt] = mnA; mB[mt] = mnB;
        }

        // O += P @ V : S C-frag IS the PV A-frag; V frags via ldmatrix
        #pragma unroll
        for (int kk = 0; kk < 4; kk++) {
            uint32_t sw = ((2u*kk + hs) ^ cx) << 4;
            uint32_t Af[2][4];
            #pragma unroll
            for (int mt = 0; mt < 2; mt++) {
                Af[mt][0] = packh2(sc[mt][2*kk][0],   sc[mt][2*kk][1]);
                Af[mt][1] = packh2(sc[mt][2*kk][2],   sc[mt][2*kk][3]);
                Af[mt][2] = packh2(sc[mt][2*kk+1][0], sc[mt][2*kk+1][1]);
                Af[mt][3] = packh2(sc[mt][2*kk+1][2], sc[mt][2*kk+1][3]);
            }
            uint32_t vb[4][4];
            #pragma unroll
            for (int p = 0; p < 4; p++) ldsm4(vb[p], sV + r128[p] + sw);
            #pragma unroll
            for (int p = 0; p < 4; p++) {
                #pragma unroll
                for (int mt = 0; mt < 2; mt++) {
                    mma_f16(oacc[mt][2*p],   Af[mt][0], Af[mt][1], Af[mt][2], Af[mt][3],
                            vb[p][0], vb[p][2]);
                    mma_f16(oacc[mt][2*p+1], Af[mt][0], Af[mt][1], Af[mt][2], Af[mt][3],
                            vb[p][1], vb[p][3]);
                }
            }
        }
    }

    // finalize
    #pragma unroll
    for (int mt = 0; mt < 2; mt++) {
        float la = lA[mt], lb = lB[mt];
        la += __shfl_xor_sync(0xffffffffu, la, 1);
        la += __shfl_xor_sync(0xffffffffu, la, 2);
        lb += __shfl_xor_sync(0xffffffffu, lb, 1);
        lb += __shfl_xor_sync(0xffffffffu, lb, 2);
        float iA = 1.f / la, iB = 1.f / lb;

        __half* OA = g_O + ((long)(b*SEQ) + qn + mt*16 + g) * BDIM + h*HD;
        __half* OB = OA + 8*BDIM;
        #pragma unroll
        for (int nt = 0; nt < 8; nt++) {
            int c = nt*8 + 2*t;
            *(uint32_t*)(OA + c) = packh2(oacc[mt][nt][0]*iA, oacc[mt][nt][1]*iA);
            *(uint32_t*)(OB + c) = packh2(oacc[mt][nt][2]*iB, oacc[mt][nt][3]*iB);
        }
    }
}

// ---------------------------------------------------------------------------
extern "C" void kernel_launch(void* const* d_in, const int* in_sizes, int n_in,
                              void* d_out, int out_size)
{
    const float* x      = (const float*)d_in[0];
    const float* qkv_w  = (const float*)d_in[1];
    const float* qkv_b  = (const float*)d_in[2];
    const float* proj_w = (const float*)d_in[3];
    const float* proj_b = (const float*)d_in[4];
    float* out = (float*)d_out;

    int shmem  = NST * STG;      // 98304
    int ashmem = ANST * ABUF;    // 49152
    cudaFuncSetAttribute(gemm_h<0>, cudaFuncAttributeMaxDynamicSharedMemorySize, shmem);
    cudaFuncSetAttribute(gemm_h<1>, cudaFuncAttributeMaxDynamicSharedMemorySize, shmem);
    cudaFuncSetAttribute(attn_h, cudaFuncAttributeMaxDynamicSharedMemorySize, ashmem);

    half_prep<<<(int)(N4_TOT/256), 256>>>(x, qkv_w, proj_w);

    dim3 g_qkv(3*BDIM/128, MTOT/128);   // (24, 32)
    gemm_h<0><<<g_qkv, 256, shmem>>>(qkv_b, nullptr, BDIM, 3*BDIM);

    dim3 g_attn(SEQ/256, NH, BB);       // (8, 16, 2)
    attn_h<<<g_attn, 256, ashmem>>>();

    dim3 g_proj(BDIM/128, MTOT/128);    // (8, 32)
    gemm_h<1><<<g_proj, 256, shmem>>>(proj_b, out, BDIM, BDIM);
}

// round 17
// speedup vs baseline: 1.0369x; 1.0008x over previous
#include <cuda_runtime.h>
#include <cuda_fp16.h>
#include <cstdint>

#define BDIM 1024
#define NH 16
#define HD 64
#define BB 2
#define SEQ 2048
#define MTOT (BB*SEQ)
#define QK_SCALE 0.1803368801111204f   // 0.125 * log2(e)

// scratch (device globals — allocation-guard safe). Referenced ONLY from
// device code (host-passing gives host shadow addrs — the R4/R5 bug).
__device__ __half g_Q [(long)BB*NH*SEQ*HD];     // Q pre-scaled by QK_SCALE
__device__ __half g_K [(long)BB*NH*SEQ*HD];
__device__ __half g_V [(long)BB*NH*SEQ*HD];     // V row-major [b,h,n,d]
__device__ __half g_O [(long)MTOT*BDIM];        // attention out, head-concat
__device__ __half g_Xh[(long)MTOT*BDIM];
__device__ __half g_Wh[(long)3*BDIM*BDIM];
__device__ __half g_PWh[(long)BDIM*BDIM];

// ---------------------------------------------------------------------------
// helpers
// ---------------------------------------------------------------------------
__device__ __forceinline__ float ex2f(float x) {
    float y;
    asm("ex2.approx.ftz.f32 %0, %1;" : "=f"(y) : "f"(x));
    return y;
}
__device__ __forceinline__ uint32_t smem_u32(const void* p) {
    uint32_t a;
    asm("{ .reg .u64 t; cvta.to.shared.u64 t, %1; cvt.u32.u64 %0, t; }" : "=r"(a) : "l"(p));
    return a;
}
__device__ __forceinline__ void cp16(uint32_t dst, const void* src) {
    asm volatile("cp.async.cg.shared.global [%0], [%1], 16;" :: "r"(dst), "l"(src) : "memory");
}
__device__ __forceinline__ uint32_t packh2(float lo, float hi) {
    __half2 h = __floats2half2_rn(lo, hi);
    return *(uint32_t*)&h;
}
__device__ __forceinline__ void ldsm4(uint32_t* r, uint32_t addr) {
    asm volatile("ldmatrix.sync.aligned.m8n8.x4.shared.b16 {%0,%1,%2,%3}, [%4];"
                 : "=r"(r[0]), "=r"(r[1]), "=r"(r[2]), "=r"(r[3]) : "r"(addr));
}
__device__ __forceinline__ void ldsm4t(uint32_t* r, uint32_t addr) {
    asm volatile("ldmatrix.sync.aligned.m8n8.x4.trans.shared.b16 {%0,%1,%2,%3}, [%4];"
                 : "=r"(r[0]), "=r"(r[1]), "=r"(r[2]), "=r"(r[3]) : "r"(addr));
}
// mma.sync m16n8k16 f16 -> f32
__device__ __forceinline__ void mma_f16(float c[4],
                                        uint32_t a0, uint32_t a1, uint32_t a2, uint32_t a3,
                                        uint32_t b0, uint32_t b1) {
    asm volatile(
        "mma.sync.aligned.m16n8k16.row.col.f32.f16.f16.f32 "
        "{%0,%1,%2,%3}, {%4,%5,%6,%7}, {%8,%9}, {%0,%1,%2,%3};"
        : "+f"(c[0]), "+f"(c[1]), "+f"(c[2]), "+f"(c[3])
        : "r"(a0), "r"(a1), "r"(a2), "r"(a3), "r"(b0), "r"(b1));
}

// ---------------------------------------------------------------------------
// prepass: fp32 -> fp16 copies of x, qkv_w, proj_w (flat, memory-shaped)
// ---------------------------------------------------------------------------
#define N4_X  ((long)MTOT*BDIM/4)
#define N4_W  ((long)3*BDIM*BDIM/4)
#define N4_PW ((long)BDIM*BDIM/4)
#define N4_TOT (N4_X + N4_W + N4_PW)

__global__ __launch_bounds__(256)
void half_prep(const float* __restrict__ x, const float* __restrict__ w,
               const float* __restrict__ pw)
{
    long i = (long)blockIdx.x*blockDim.x + threadIdx.x;
    const float4* src;
    uint2* dst;
    long off;
    if (i < N4_X)             { src = (const float4*)x;  dst = (uint2*)g_Xh;  off = i; }
    else if (i < N4_X + N4_W) { src = (const float4*)w;  dst = (uint2*)g_Wh;  off = i - N4_X; }
    else                      { src = (const float4*)pw; dst = (uint2*)g_PWh; off = i - N4_X - N4_W; }
    float4 v = src[off];
    uint2 u;
    u.x = packh2(v.x, v.y);
    u.y = packh2(v.z, v.w);
    dst[off] = u;
}

// ---------------------------------------------------------------------------
// FP16 GEMM — R9 configuration (proven best): block 128x128, Ktile 64,
// 256 thr (8 warps, warp tile 64x32), ldmatrix + cp.async 3-stage, SW128,
// 2 CTAs/SM. V now stored row-major (coalesced, same as K) — no scatter.
// ---------------------------------------------------------------------------
#define STG_OP 16384             // 128 rows x 128B
#define STG    32768
#define NST    3                 // 96 KB

template<int MODE>
__global__ __launch_bounds__(256, 2)
void gemm_h(const float* __restrict__ bias, float* __restrict__ Cout,
            int K, int Nout)
{
    extern __shared__ char smem[];
    uint32_t sbase = smem_u32(smem);
    const __half* Ab = (MODE == 1) ? (const __half*)g_O  : (const __half*)g_Xh;
    const __half* Wb = (MODE == 1) ? (const __half*)g_PWh : (const __half*)g_Wh;

    int tid = threadIdx.x, warp = tid >> 5, lane = tid & 31;
    int g = lane >> 2, t = lane & 3;
    int wm = (warp >> 2) * 64, wn = (warp & 3) * 32;
    int m0 = blockIdx.y * 128, n0 = blockIdx.x * 128;

    const __half* asrc[4];
    const __half* bsrc[4];
    uint32_t doff[4];
    #pragma unroll
    for (int i = 0; i < 4; i++) {
        int cid = i*256 + tid;
        int row = cid >> 3, ch = cid & 7;
        doff[i] = (uint32_t)(row*128 + ((ch ^ (row & 7)) << 4));
        asrc[i] = Ab + (long)(m0 + row)*K + ch*8;
        bsrc[i] = Wb + (long)(n0 + row)*K + ch*8;
    }

    int lr16 = lane & 15;
    uint32_t hs = (uint32_t)(lane >> 4);
    uint32_t cx = (uint32_t)(lane & 7);
    uint32_t ar128[4], br128[2];
    #pragma unroll
    for (int mt = 0; mt < 4; mt++) ar128[mt] = (uint32_t)(wm + mt*16 + lr16) * 128u;
    #pragma unroll
    for (int p = 0; p < 2; p++)    br128[p] = (uint32_t)(wn + p*16 + lr16) * 128u;

    float acc[4][4][4];
    #pragma unroll
    for (int i = 0; i < 4; i++)
        #pragma unroll
        for (int j = 0; j < 4; j++)
            #pragma unroll
            for (int c = 0; c < 4; c++) acc[i][j][c] = 0.f;

    int niter = K >> 6;

    #pragma unroll
    for (int s = 0; s < 2; s++) {
        uint32_t db = sbase + s*STG;
        #pragma unroll
        for (int i = 0; i < 4; i++) {
            cp16(db + doff[i],          asrc[i] + s*64);
            cp16(db + STG_OP + doff[i], bsrc[i] + s*64);
        }
        asm volatile("cp.async.commit_group;" ::: "memory");
    }

    for (int it = 0; it < niter; ++it) {
        asm volatile("cp.async.wait_group 1;" ::: "memory");
        __syncthreads();

        int nx = it + 2;
        if (nx < niter) {
            uint32_t db = sbase + (nx % NST)*STG;
            long koff = (long)nx * 64;
            #pragma unroll
            for (int i = 0; i < 4; i++) {
                cp16(db + doff[i],          asrc[i] + koff);
                cp16(db + STG_OP + doff[i], bsrc[i] + koff);
            }
        }
        asm volatile("cp.async.commit_group;" ::: "memory");

        uint32_t sA = sbase + (it % NST)*STG;
        uint32_t sB = sA + STG_OP;

        #pragma unroll
        for (int kk = 0; kk < 4; kk++) {
            uint32_t sw = ((2u*kk + hs) ^ cx) << 4;
            uint32_t af[4][4], bf[2][4];
            #pragma unroll
            for (int mt = 0; mt < 4; mt++) ldsm4(af[mt], sA + ar128[mt] + sw);
            #pragma unroll
            for (int p = 0; p < 2; p++)    ldsm4(bf[p], sB + br128[p] + sw);
            #pragma unroll
            for (int mt = 0; mt < 4; mt++) {
                #pragma unroll
                for (int p = 0; p < 2; p++) {
                    mma_f16(acc[mt][2*p],   af[mt][0], af[mt][1], af[mt][2], af[mt][3],
                            bf[p][0], bf[p][2]);
                    mma_f16(acc[mt][2*p+1], af[mt][0], af[mt][1], af[mt][2], af[mt][3],
                            bf[p][1], bf[p][3]);
                }
            }
        }
    }

    #pragma unroll
    for (int mt = 0; mt < 4; mt++) {
        int rowA = m0 + wm + mt*16 + g;
        int rowB = rowA + 8;
        #pragma unroll
        for (int nt = 0; nt < 4; nt++) {
            int col = n0 + wn + nt*8 + 2*t;
            float b0v = bias[col], b1v = bias[col+1];
            float2 va = make_float2(acc[mt][nt][0] + b0v, acc[mt][nt][1] + b1v);
            float2 vb = make_float2(acc[mt][nt][2] + b0v, acc[mt][nt][3] + b1v);
            if (MODE == 0) {
                int which = col >> 10;
                int c = col & (BDIM - 1);
                int hh = c >> 6, d = c & 63;
                int bA = rowA >> 11, nA = rowA & (SEQ - 1);
                int bR = rowB >> 11, nR = rowB & (SEQ - 1);
                if (which == 0) {
                    va.x *= QK_SCALE; va.y *= QK_SCALE;
                    vb.x *= QK_SCALE; vb.y *= QK_SCALE;
                }
                __half* dst = (which == 0) ? g_Q : (which == 1) ? g_K : g_V;
                *(uint32_t*)(dst + ((((long)bA*NH + hh)*SEQ) + nA)*HD + d) = packh2(va.x, va.y);
                *(uint32_t*)(dst + ((((long)bR*NH + hh)*SEQ) + nR)*HD + d) = packh2(vb.x, vb.y);
            } else {
                *(float2*)(Cout + (long)rowA * Nout + col) = va;
                *(float2*)(Cout + (long)rowB * Nout + col) = vb;
            }
        }
    }
}

// ---------------------------------------------------------------------------
// FP16 flash attention — R9 structure; V now stored row-major like K and
// loaded with ldmatrix.trans (delivers the exact B-fragment the PV mma
// needs; matrix pairing (r0,r1)/(r2,r3) since trans swaps the index that
// runs along the register pair). 8 warps x 32 q-rows, 64-key tiles, SW128,
// cp.async 3-stage. S C-frag == PV A-frag identity.
// ---------------------------------------------------------------------------
#define KBY 8192                     // 64 rows x 128B
#define ABUF (2*KBY)
#define ANST 3                       // 48 KB

__global__ __launch_bounds__(256, 1)
void attn_h()
{
    extern __shared__ __align__(16) char dsm[];

    int tid  = threadIdx.x;
    int lane = tid & 31, warp = tid >> 5;      // warp 0..7
    int g = lane >> 2, t = lane & 3;
    int b = blockIdx.z, h = blockIdx.y;
    const __half* Qb = g_Q + ((long)(b*NH + h)) * SEQ * HD;
    const __half* Kb = g_K + ((long)(b*NH + h)) * SEQ * HD;
    const __half* Vb = g_V + ((long)(b*NH + h)) * SEQ * HD;

    int qn = blockIdx.x * 256 + warp * 32;

    uint32_t sb = smem_u32(dsm);
    uint32_t kdo[2];
    const __half* ksrc[2];
    const __half* vsrc[2];
    #pragma unroll
    for (int i = 0; i < 2; i++) {
        int cid = i*256 + tid;
        int row = cid >> 3, ch = cid & 7;          // row 0..63 (key)
        kdo[i] = (uint32_t)(row*128 + ((ch ^ (row & 7)) << 4));
        ksrc[i] = Kb + (long)row*HD + ch*8;        // +64*HD per tile
        vsrc[i] = Vb + (long)row*HD + ch*8;        // +64*HD per tile
    }

    int lr16 = lane & 15;
    uint32_t hs = (uint32_t)(lane >> 4);
    uint32_t cx = (uint32_t)(lane & 7);
    uint32_t r128[4];
    #pragma unroll
    for (int p = 0; p < 4; p++) r128[p] = (uint32_t)(p*16 + lr16) * 128u;

    uint32_t qf[4][2][4];
    #pragma unroll
    for (int mt = 0; mt < 2; mt++) {
        const uint32_t* q0 = (const uint32_t*)(Qb + (long)(qn + mt*16 + g) * HD);
        const uint32_t* q1 = (const uint32_t*)(Qb + (long)(qn + mt*16 + g + 8) * HD);
        #pragma unroll
        for (int kk = 0; kk < 4; kk++) {
            qf[kk][mt][0] = q0[kk*8 + t];
            qf[kk][mt][1] = q1[kk*8 + t];
            qf[kk][mt][2] = q0[kk*8 + t + 4];
            qf[kk][mt][3] = q1[kk*8 + t + 4];
        }
    }

    float oacc[2][8][4];
    #pragma unroll
    for (int mt = 0; mt < 2; mt++)
        #pragma unroll
        for (int i = 0; i < 8; i++)
            #pragma unroll
            for (int j = 0; j < 4; j++) oacc[mt][i][j] = 0.f;
    float mA[2] = {-1e30f, -1e30f}, mB[2] = {-1e30f, -1e30f};
    float lA[2] = {0.f, 0.f},       lB[2] = {0.f, 0.f};

    #pragma unroll
    for (int s = 0; s < 2; s++) {
        uint32_t so = (uint32_t)s * ABUF;
        #pragma unroll
        for (int i = 0; i < 2; i++) {
            cp16(sb + so + kdo[i],       ksrc[i] + (long)s*64*HD);
            cp16(sb + so + KBY + kdo[i], vsrc[i] + (long)s*64*HD);
        }
        asm volatile("cp.async.commit_group;" ::: "memory");
    }

    const int NT = SEQ/64;
    for (int kt = 0; kt < NT; ++kt) {
        asm volatile("cp.async.wait_group 1;" ::: "memory");
        __syncthreads();

        if (kt + 2 < NT) {
            uint32_t so = (uint32_t)((kt+2) % ANST) * ABUF;
            #pragma unroll
            for (int i = 0; i < 2; i++) {
                cp16(sb + so + kdo[i],       ksrc[i] + (long)(kt+2)*64*HD);
                cp16(sb + so + KBY + kdo[i], vsrc[i] + (long)(kt+2)*64*HD);
            }
        }
        asm volatile("cp.async.commit_group;" ::: "memory");

        uint32_t sK = sb + (kt % ANST)*ABUF;
        uint32_t sV = sK + KBY;

        // S = Q @ K^T (log2 units)
        float sc[2][8][4];
        #pragma unroll
        for (int mt = 0; mt < 2; mt++)
            #pragma unroll
            for (int i = 0; i < 8; i++)
                #pragma unroll
                for (int j = 0; j < 4; j++) sc[mt][i][j] = 0.f;
        #pragma unroll
        for (int kk = 0; kk < 4; kk++) {
            uint32_t sw = ((2u*kk + hs) ^ cx) << 4;
            uint32_t kb[4][4];
            #pragma unroll
            for (int p = 0; p < 4; p++) ldsm4(kb[p], sK + r128[p] + sw);
            #pragma unroll
            for (int p = 0; p < 4; p++) {
                #pragma unroll
                for (int mt = 0; mt < 2; mt++) {
                    mma_f16(sc[mt][2*p],   qf[kk][mt][0], qf[kk][mt][1], qf[kk][mt][2], qf[kk][mt][3],
                            kb[p][0], kb[p][2]);
                    mma_f16(sc[mt][2*p+1], qf[kk][mt][0], qf[kk][mt][1], qf[kk][mt][2], qf[kk][mt][3],
                            kb[p][1], kb[p][3]);
                }
            }
        }

        // online softmax per m-tile
        #pragma unroll
        for (int mt = 0; mt < 2; mt++) {
            float mlA = -1e30f, mlB = -1e30f;
            #pragma unroll
            for (int nt = 0; nt < 8; nt++) {
                mlA = fmaxf(mlA, fmaxf(sc[mt][nt][0], sc[mt][nt][1]));
                mlB = fmaxf(mlB, fmaxf(sc[mt][nt][2], sc[mt][nt][3]));
            }
            mlA = fmaxf(mlA, __shfl_xor_sync(0xffffffffu, mlA, 1));
            mlA = fmaxf(mlA, __shfl_xor_sync(0xffffffffu, mlA, 2));
            mlB = fmaxf(mlB, __shfl_xor_sync(0xffffffffu, mlB, 1));
            mlB = fmaxf(mlB, __shfl_xor_sync(0xffffffffu, mlB, 2));
            float mnA = fmaxf(mA[mt], mlA), mnB = fmaxf(mB[mt], mlB);
            float cA = ex2f(mA[mt] - mnA), cB = ex2f(mB[mt] - mnB);
            lA[mt] *= cA; lB[mt] *= cB;
            #pragma unroll
            for (int nt = 0; nt < 8; nt++) {
                oacc[mt][nt][0] *= cA; oacc[mt][nt][1] *= cA;
                oacc[mt][nt][2] *= cB; oacc[mt][nt][3] *= cB;
            }
            #pragma unroll
            for (int nt = 0; nt < 8; nt++) {
                float p0 = ex2f(sc[mt][nt][0] - mnA);
                float p1 = ex2f(sc[mt][nt][1] - mnA);
                float p2 = ex2f(sc[mt][nt][2] - mnB);
                float p3 = ex2f(sc[mt][nt][3] - mnB);
                lA[mt] += p0 + p1; lB[mt] += p2 + p3;
                sc[mt][nt][0] = p0; sc[mt][nt][1] = p1;
                sc[mt][nt][2] = p2; sc[mt][nt][3] = p3;
            }
            mA[mt] = mnA; mB[mt] = mnB;
        }

        // O += P @ V : V row-major in smem (rows = keys), loaded with
        // ldmatrix.trans. Row base for k-step kk = kk*16 (reuses r128[kk]).
        #pragma unroll
        for (int kk = 0; kk < 4; kk++) {
            uint32_t Af[2][4];
            #pragma unroll
            for (int mt = 0; mt < 2; mt++) {
                Af[mt][0] = packh2(sc[mt][2*kk][0],   sc[mt][2*kk][1]);
                Af[mt][1] = packh2(sc[mt][2*kk][2],   sc[mt][2*kk][3]);
                Af[mt][2] = packh2(sc[mt][2*kk+1][0], sc[mt][2*kk+1][1]);
                Af[mt][3] = packh2(sc[mt][2*kk+1][2], sc[mt][2*kk+1][3]);
            }
            #pragma unroll
            for (int j = 0; j < 4; j++) {       // d-chunk pair -> nt = 2j, 2j+1
                uint32_t sw = ((2u*j + hs) ^ cx) << 4;
                uint32_t vb4[4];
                ldsm4t(vb4, sV + r128[kk] + sw);
                #pragma unroll
                for (int mt = 0; mt < 2; mt++) {
                    mma_f16(oacc[mt][2*j],   Af[mt][0], Af[mt][1], Af[mt][2], Af[mt][3],
                            vb4[0], vb4[1]);
                    mma_f16(oacc[mt][2*j+1], Af[mt][0], Af[mt][1], Af[mt][2], Af[mt][3],
                            vb4[2], vb4[3]);
                }
            }
        }
    }

    // finalize
    #pragma unroll
    for (int mt = 0; mt < 2; mt++) {
        float la = lA[mt], lb = lB[mt];
        la += __shfl_xor_sync(0xffffffffu, la, 1);
        la += __shfl_xor_sync(0xffffffffu, la, 2);
        lb += __shfl_xor_sync(0xffffffffu, lb, 1);
        lb += __shfl_xor_sync(0xffffffffu, lb, 2);
        float iA = 1.f / la, iB = 1.f / lb;

        __half* OA = g_O + ((long)(b*SEQ) + qn + mt*16 + g) * BDIM + h*HD;
        __half* OB = OA + 8*BDIM;
        #pragma unroll
        for (int nt = 0; nt < 8; nt++) {
            int c = nt*8 + 2*t;
            *(uint32_t*)(OA + c) = packh2(oacc[mt][nt][0]*iA, oacc[mt][nt][1]*iA);
            *(uint32_t*)(OB + c) = packh2(oacc[mt][nt][2]*iB, oacc[mt][nt][3]*iB);
        }
    }
}

// ---------------------------------------------------------------------------
extern "C" void kernel_launch(void* const* d_in, const int* in_sizes, int n_in,
                              void* d_out, int out_size)
{
    const float* x      = (const float*)d_in[0];
    const float* qkv_w  = (const float*)d_in[1];
    const float* qkv_b  = (const float*)d_in[2];
    const float* proj_w = (const float*)d_in[3];
    const float* proj_b = (const float*)d_in[4];
    float* out = (float*)d_out;

    int shmem  = NST * STG;      // 98304
    int ashmem = ANST * ABUF;    // 49152
    cudaFuncSetAttribute(gemm_h<0>, cudaFuncAttributeMaxDynamicSharedMemorySize, shmem);
    cudaFuncSetAttribute(gemm_h<1>, cudaFuncAttributeMaxDynamicSharedMemorySize, shmem);
    cudaFuncSetAttribute(attn_h, cudaFuncAttributeMaxDynamicSharedMemorySize, ashmem);

    half_prep<<<(int)(N4_TOT/256), 256>>>(x, qkv_w, proj_w);

    dim3 g_qkv(3*BDIM/128, MTOT/128);   // (24, 32)
    gemm_h<0><<<g_qkv, 256, shmem>>>(qkv_b, nullptr, BDIM, 3*BDIM);

    dim3 g_attn(SEQ/256, NH, BB);       // (8, 16, 2)
    attn_h<<<g_attn, 256, ashmem>>>();

    dim3 g_proj(BDIM/128, MTOT/128);    // (8, 32)
    gemm_h<1><<<g_proj, 256, shmem>>>(proj_b, out, BDIM, BDIM);
}